// round 2
// baseline (speedup 1.0000x reference)
#include <cuda_runtime.h>
#include <math.h>

// KineticsRNN: persistent per-CTA recurrence, fp32 throughout.
// 128 CTAs x 4 batch elements, 384 threads (one thread per GRU gate row).
// W_hh in shared (padded pitch 132 for conflict-free LDS.128),
// W_ih / W_head / W_lift rows in registers for the whole K loop.

#define THREADS 384
#define HDIM 128
#define LDIM 32
#define PITCH 132   // 128 + 4 words: conflict-free LDS.128 across lanes

// shared floats: Whh + h + lift + r + z + theta + u + yobs + ytf
#define SMEM_FLOATS (384*PITCH + 4*HDIM + 4*LDIM + 4*HDIM + 4*HDIM + 32 + 16 + 16 + 16)
#define SMEM_BYTES  (SMEM_FLOATS * 4)

__device__ __forceinline__ float sigm(float x) { return 1.0f / (1.0f + expf(-x)); }

__global__ __launch_bounds__(THREADS, 1)
void krnn_kernel(const float* __restrict__ y0,
                 const float* __restrict__ u_seq,
                 const float* __restrict__ dt_seq,
                 const float* __restrict__ y_seq,
                 const float* __restrict__ W_lift,
                 const float* __restrict__ b_lift,
                 const float* __restrict__ W_ih,
                 const float* __restrict__ W_hh,
                 const float* __restrict__ b_ih,
                 const float* __restrict__ b_hh,
                 const float* __restrict__ W_head,
                 const float* __restrict__ b_head,
                 const float* __restrict__ u2y,
                 float* __restrict__ out,
                 int B, int K)
{
    extern __shared__ float sm[];
    float* sWhh   = sm;                      // 384*PITCH
    float* sH     = sWhh + 384 * PITCH;      // 4*128
    float* sLift  = sH + 4 * HDIM;           // 4*32
    float* sR     = sLift + 4 * LDIM;        // 4*128
    float* sZ     = sR + 4 * HDIM;           // 4*128
    float* sTheta = sZ + 4 * HDIM;           // 4*8
    float* sU     = sTheta + 32;             // 4*4
    float* sYobs  = sU + 16;                 // 4*4
    float* sYtf   = sYobs + 16;              // 4*4

    const int t   = threadIdx.x;
    const int bg0 = blockIdx.x * 4;

    // ---- stage W_hh (384x128) into padded shared, float4 granularity ----
    {
        const float4* src = (const float4*)W_hh;
        for (int idx = t; idx < 384 * (HDIM / 4); idx += THREADS) {
            int row = idx >> 5;          // 32 float4 per row
            int cb  = idx & 31;
            *(float4*)(sWhh + row * PITCH + cb * 4) = src[idx];
        }
    }

    // ---- W_ih row t in registers (held across all K steps) ----
    float wih[LDIM];
    {
        const float4* p = (const float4*)(W_ih + t * LDIM);
#pragma unroll
        for (int i = 0; i < LDIM / 4; i++) {
            float4 v = p[i];
            wih[4 * i + 0] = v.x; wih[4 * i + 1] = v.y;
            wih[4 * i + 2] = v.z; wih[4 * i + 3] = v.w;
        }
    }
    const float bi = b_ih[t];
    const float bh = b_hh[t];

    // ---- lift weights (threads 0..127: row lr, batch lb) ----
    const int lr = t >> 2, lb = t & 3;
    float wl0 = 0, wl1 = 0, wl2 = 0, wl3 = 0, wl4 = 0, wl5 = 0, blf = 0;
    if (t < 128) {
        wl0 = W_lift[lr * 6 + 0]; wl1 = W_lift[lr * 6 + 1]; wl2 = W_lift[lr * 6 + 2];
        wl3 = W_lift[lr * 6 + 3]; wl4 = W_lift[lr * 6 + 4]; wl5 = W_lift[lr * 6 + 5];
        blf = b_lift[lr];
    }

    // ---- head weights (threads 0..159: 20 groups of 8 lanes; group = (param, batch)) ----
    const int tg = t >> 3, tl = t & 7;
    const int tp = tg % 5, tb = tg / 5;
    float wh[16]; float bhd = 0.f;
    if (t < 160) {
        const float4* p = (const float4*)(W_head + tp * HDIM + tl * 16);
#pragma unroll
        for (int i = 0; i < 4; i++) {
            float4 v = p[i];
            wh[4 * i + 0] = v.x; wh[4 * i + 1] = v.y;
            wh[4 * i + 2] = v.z; wh[4 * i + 3] = v.w;
        }
        bhd = b_head[tp];
    } else {
#pragma unroll
        for (int i = 0; i < 16; i++) wh[i] = 0.f;
    }

    // ---- RK4 thread state (threads 0..3, one per batch elem): y_full in regs ----
    float yf0 = 0, yf1 = 0, yf2 = 0, yf3 = 0, yf4 = 0;
    float J00 = 0, J01 = 0, J02 = 0, J10 = 0, J11 = 0, J12 = 0, J20 = 0, J21 = 0, J22 = 0;
    float cu0 = 0, cu1 = 0, cu2 = 0, cdt = 0;
    if (t < 4) {
        int bg = bg0 + t;
        yf0 = y0[bg * 3 + 0]; yf2 = y0[bg * 3 + 1]; yf4 = y0[bg * 3 + 2];
        J00 = u2y[0]; J01 = u2y[1]; J02 = u2y[2];
        J10 = u2y[3]; J11 = u2y[4]; J12 = u2y[5];
        J20 = u2y[6]; J21 = u2y[7]; J22 = u2y[8];
        const float* up = u_seq + (size_t)bg * K * 3;
        cu0 = up[0]; cu1 = up[1]; cu2 = up[2];
        cdt = dt_seq[(size_t)bg * K];
        sU[t * 4 + 0] = cu0; sU[t * 4 + 1] = cu1; sU[t * 4 + 2] = cu2;
        sYobs[t * 4 + 0] = yf0; sYobs[t * 4 + 1] = yf2; sYobs[t * 4 + 2] = yf4;
    }
    for (int i = t; i < 4 * HDIM; i += THREADS) sH[i] = 0.f;
    __syncthreads();

    const size_t theta_base = (size_t)B * K * 3;

    for (int k = 0; k < K; k++) {
        const bool flag = (k > 0) && (k % 50 == 0);

        // ---- prefetch next-step inputs (fire LDGs now, commit to smem in Phase E) ----
        float nu0 = 0, nu1 = 0, nu2 = 0, ndt = 0, nt0 = 0, nt1 = 0, nt2 = 0;
        bool nflag = false;
        if (t < 4 && (k + 1) < K) {
            int bg = bg0 + t;
            const float* up = u_seq + ((size_t)bg * K + (k + 1)) * 3;
            nu0 = up[0]; nu1 = up[1]; nu2 = up[2];
            ndt = dt_seq[(size_t)bg * K + (k + 1)];
            nflag = ((k + 1) % 50) == 0;
            if (nflag) {
                const float* yp = y_seq + ((size_t)bg * K + k) * 3;  // y_tf(k+1) = y_seq[:,k]
                nt0 = yp[0]; nt1 = yp[1]; nt2 = yp[2];
            }
        }

        // ---- Phase A: lift = silu(W_lift @ [u, y_in]) ----
        if (t < 128) {
            const float* ub = sU + lb * 4;
            const float* yb = flag ? (sYtf + lb * 4) : (sYobs + lb * 4);
            float s = blf;
            s = fmaf(wl0, ub[0], s); s = fmaf(wl1, ub[1], s); s = fmaf(wl2, ub[2], s);
            s = fmaf(wl3, yb[0], s); s = fmaf(wl4, yb[1], s); s = fmaf(wl5, yb[2], s);
            sLift[lb * LDIM + lr] = s * sigm(s);
        }
        __syncthreads();

        // ---- Phase B: gx = W_ih@lift (regs x smem), gh = W_hh@h (smem x smem) ----
        float ax0 = 0, ax1 = 0, ax2 = 0, ax3 = 0;
        {
            const float4* l0 = (const float4*)(sLift);
            const float4* l1 = (const float4*)(sLift + LDIM);
            const float4* l2 = (const float4*)(sLift + 2 * LDIM);
            const float4* l3 = (const float4*)(sLift + 3 * LDIM);
#pragma unroll
            for (int jb = 0; jb < LDIM / 4; jb++) {
                float w0 = wih[4 * jb], w1 = wih[4 * jb + 1], w2 = wih[4 * jb + 2], w3 = wih[4 * jb + 3];
                float4 a = l0[jb];
                ax0 = fmaf(w0, a.x, ax0); ax0 = fmaf(w1, a.y, ax0); ax0 = fmaf(w2, a.z, ax0); ax0 = fmaf(w3, a.w, ax0);
                float4 b4 = l1[jb];
                ax1 = fmaf(w0, b4.x, ax1); ax1 = fmaf(w1, b4.y, ax1); ax1 = fmaf(w2, b4.z, ax1); ax1 = fmaf(w3, b4.w, ax1);
                float4 c = l2[jb];
                ax2 = fmaf(w0, c.x, ax2); ax2 = fmaf(w1, c.y, ax2); ax2 = fmaf(w2, c.z, ax2); ax2 = fmaf(w3, c.w, ax2);
                float4 d = l3[jb];
                ax3 = fmaf(w0, d.x, ax3); ax3 = fmaf(w1, d.y, ax3); ax3 = fmaf(w2, d.z, ax3); ax3 = fmaf(w3, d.w, ax3);
            }
        }
        float ah0 = 0, ah1 = 0, ah2 = 0, ah3 = 0;
        {
            const float4* wr = (const float4*)(sWhh + t * PITCH);
            const float4* h0 = (const float4*)(sH);
            const float4* h1 = (const float4*)(sH + HDIM);
            const float4* h2 = (const float4*)(sH + 2 * HDIM);
            const float4* h3 = (const float4*)(sH + 3 * HDIM);
#pragma unroll
            for (int jb = 0; jb < HDIM / 4; jb++) {
                float4 w = wr[jb];
                float4 a = h0[jb];
                ah0 = fmaf(w.x, a.x, ah0); ah0 = fmaf(w.y, a.y, ah0); ah0 = fmaf(w.z, a.z, ah0); ah0 = fmaf(w.w, a.w, ah0);
                float4 b4 = h1[jb];
                ah1 = fmaf(w.x, b4.x, ah1); ah1 = fmaf(w.y, b4.y, ah1); ah1 = fmaf(w.z, b4.z, ah1); ah1 = fmaf(w.w, b4.w, ah1);
                float4 c = h2[jb];
                ah2 = fmaf(w.x, c.x, ah2); ah2 = fmaf(w.y, c.y, ah2); ah2 = fmaf(w.z, c.z, ah2); ah2 = fmaf(w.w, c.w, ah2);
                float4 d = h3[jb];
                ah3 = fmaf(w.x, d.x, ah3); ah3 = fmaf(w.y, d.y, ah3); ah3 = fmaf(w.z, d.z, ah3); ah3 = fmaf(w.w, d.w, ah3);
            }
        }

        float gxn0 = 0, gxn1 = 0, gxn2 = 0, gxn3 = 0;
        float ghn0 = 0, ghn1 = 0, ghn2 = 0, ghn3 = 0;
        if (t < 2 * HDIM) {
            // r rows (0..127) and z rows (128..255): biases combine
            float cst = bi + bh;
            float* base = (t < HDIM) ? sR : sZ;
            int i = (t < HDIM) ? t : (t - HDIM);
            base[0 * HDIM + i] = sigm(ax0 + ah0 + cst);
            base[1 * HDIM + i] = sigm(ax1 + ah1 + cst);
            base[2 * HDIM + i] = sigm(ax2 + ah2 + cst);
            base[3 * HDIM + i] = sigm(ax3 + ah3 + cst);
        } else {
            // n rows: keep gx and gh separate (n = tanh(gxn + r*ghn))
            gxn0 = ax0 + bi; gxn1 = ax1 + bi; gxn2 = ax2 + bi; gxn3 = ax3 + bi;
            ghn0 = ah0 + bh; ghn1 = ah1 + bh; ghn2 = ah2 + bh; ghn3 = ah3 + bh;
        }
        __syncthreads();

        // ---- Phase C: n, h_new (threads 256..383, hidden index i) ----
        if (t >= 256) {
            int i = t - 256;
            {
                float r = sR[0 * HDIM + i]; float n = tanhf(fmaf(r, ghn0, gxn0));
                float z = sZ[0 * HDIM + i]; float ho = sH[0 * HDIM + i];
                sH[0 * HDIM + i] = (1.0f - z) * n + z * ho;
            }
            {
                float r = sR[1 * HDIM + i]; float n = tanhf(fmaf(r, ghn1, gxn1));
                float z = sZ[1 * HDIM + i]; float ho = sH[1 * HDIM + i];
                sH[1 * HDIM + i] = (1.0f - z) * n + z * ho;
            }
            {
                float r = sR[2 * HDIM + i]; float n = tanhf(fmaf(r, ghn2, gxn2));
                float z = sZ[2 * HDIM + i]; float ho = sH[2 * HDIM + i];
                sH[2 * HDIM + i] = (1.0f - z) * n + z * ho;
            }
            {
                float r = sR[3 * HDIM + i]; float n = tanhf(fmaf(r, ghn3, gxn3));
                float z = sZ[3 * HDIM + i]; float ho = sH[3 * HDIM + i];
                sH[3 * HDIM + i] = (1.0f - z) * n + z * ho;
            }
        }
        __syncthreads();

        // ---- Phase D: theta = LO + (HI-LO)*sigmoid(W_head @ h_new + b_head) ----
        if (t < 160) {
            const float4* hb = (const float4*)(sH + tb * HDIM + tl * 16);
            float4 a = hb[0], b4 = hb[1], c = hb[2], d = hb[3];
            float s = 0.f;
            s = fmaf(wh[0],  a.x,  s); s = fmaf(wh[1],  a.y,  s); s = fmaf(wh[2],  a.z,  s); s = fmaf(wh[3],  a.w,  s);
            s = fmaf(wh[4],  b4.x, s); s = fmaf(wh[5],  b4.y, s); s = fmaf(wh[6],  b4.z, s); s = fmaf(wh[7],  b4.w, s);
            s = fmaf(wh[8],  c.x,  s); s = fmaf(wh[9],  c.y,  s); s = fmaf(wh[10], c.z,  s); s = fmaf(wh[11], c.w,  s);
            s = fmaf(wh[12], d.x,  s); s = fmaf(wh[13], d.y,  s); s = fmaf(wh[14], d.z,  s); s = fmaf(wh[15], d.w,  s);
            s += __shfl_xor_sync(0xffffffffu, s, 1);
            s += __shfl_xor_sync(0xffffffffu, s, 2);
            s += __shfl_xor_sync(0xffffffffu, s, 4);
            if (tl == 0) {
                float th = 0.001f + 1.999f * sigm(s + bhd);
                sTheta[tb * 8 + tp] = th;
                out[theta_base + ((size_t)(bg0 + tb) * K + k) * 5 + tp] = th;
            }
        }
        __syncthreads();

        // ---- Phase E: jump + RK4 + outputs + buffer rotation (threads 0..3) ----
        if (t < 4) {
            float th0 = sTheta[t * 8 + 0], th1 = sTheta[t * 8 + 1], th2 = sTheta[t * 8 + 2];
            float th3 = sTheta[t * 8 + 3], th4 = sTheta[t * 8 + 4];

            // y_jump: obs entries += u @ u_to_y_jump
            yf0 += cu0 * J00 + cu1 * J10 + cu2 * J20;
            yf2 += cu0 * J01 + cu1 * J11 + cu2 * J21;
            yf4 += cu0 * J02 + cu1 * J12 + cu2 * J22;

            float h  = cdt;
            float hh = 0.5f * h;
#define RHS(A, Bv, C, D, E, d0, d1, d2, d3, d4)                          \
            {                                                            \
                float r1 = th0 * (A) * (Bv);                             \
                float r2 = th1 * (C);                                    \
                float r3 = th2 * (C) * (D);                              \
                float r4 = th3 * (E);                                    \
                float r5 = th4 * (A);                                    \
                d0 = -r1 - r5; d1 = -r1 + r2; d2 = r1 - r2 - r3;         \
                d3 = -r3 + r4; d4 = r3 - r4 + r5;                        \
            }
            float a0, a1, a2, a3, a4;
            RHS(yf0, yf1, yf2, yf3, yf4, a0, a1, a2, a3, a4);
            float t0 = yf0 + hh * a0, t1 = yf1 + hh * a1, t2 = yf2 + hh * a2,
                  t3 = yf3 + hh * a3, t4 = yf4 + hh * a4;
            float b0, b1, b2, b3, b4v;
            RHS(t0, t1, t2, t3, t4, b0, b1, b2, b3, b4v);
            t0 = yf0 + hh * b0; t1 = yf1 + hh * b1; t2 = yf2 + hh * b2;
            t3 = yf3 + hh * b3; t4 = yf4 + hh * b4v;
            float c0, c1, c2, c3, c4;
            RHS(t0, t1, t2, t3, t4, c0, c1, c2, c3, c4);
            t0 = yf0 + h * c0; t1 = yf1 + h * c1; t2 = yf2 + h * c2;
            t3 = yf3 + h * c3; t4 = yf4 + h * c4;
            float d0, d1, d2, d3, d4;
            RHS(t0, t1, t2, t3, t4, d0, d1, d2, d3, d4);
#undef RHS
            float s6 = h * (1.0f / 6.0f);
            yf0 = fmaxf(yf0 + s6 * (a0 + 2.f * b0 + 2.f * c0 + d0), 0.f);
            yf1 = fmaxf(yf1 + s6 * (a1 + 2.f * b1 + 2.f * c1 + d1), 0.f);
            yf2 = fmaxf(yf2 + s6 * (a2 + 2.f * b2 + 2.f * c2 + d2), 0.f);
            yf3 = fmaxf(yf3 + s6 * (a3 + 2.f * b3 + 2.f * c3 + d3), 0.f);
            yf4 = fmaxf(yf4 + s6 * (a4 + 2.f * b4v + 2.f * c4 + d4), 0.f);

            int bg = bg0 + t;
            float* yo = out + ((size_t)bg * K + k) * 3;
            yo[0] = yf0; yo[1] = yf2; yo[2] = yf4;
            sYobs[t * 4 + 0] = yf0; sYobs[t * 4 + 1] = yf2; sYobs[t * 4 + 2] = yf4;

            if (k + 1 < K) {
                sU[t * 4 + 0] = nu0; sU[t * 4 + 1] = nu1; sU[t * 4 + 2] = nu2;
                if (nflag) { sYtf[t * 4 + 0] = nt0; sYtf[t * 4 + 1] = nt1; sYtf[t * 4 + 2] = nt2; }
                cu0 = nu0; cu1 = nu1; cu2 = nu2; cdt = ndt;
            }
        }
        __syncthreads();
    }
}

extern "C" void kernel_launch(void* const* d_in, const int* in_sizes, int n_in,
                              void* d_out, int out_size)
{
    const float* y0     = (const float*)d_in[0];
    const float* u_seq  = (const float*)d_in[1];
    const float* dt_seq = (const float*)d_in[2];
    const float* y_seq  = (const float*)d_in[3];
    const float* W_lift = (const float*)d_in[4];
    const float* b_lift = (const float*)d_in[5];
    const float* W_ih   = (const float*)d_in[6];
    const float* W_hh   = (const float*)d_in[7];
    const float* b_ih   = (const float*)d_in[8];
    const float* b_hh   = (const float*)d_in[9];
    const float* W_head = (const float*)d_in[10];
    const float* b_head = (const float*)d_in[11];
    const float* u2y    = (const float*)d_in[12];
    float* out = (float*)d_out;

    int B = in_sizes[0] / 3;        // y0 is (B, 3)
    int K = in_sizes[2] / B;        // dt_seq is (B, K)

    cudaFuncSetAttribute(krnn_kernel, cudaFuncAttributeMaxDynamicSharedMemorySize, SMEM_BYTES);
    krnn_kernel<<<B / 4, THREADS, SMEM_BYTES>>>(
        y0, u_seq, dt_seq, y_seq, W_lift, b_lift, W_ih, W_hh,
        b_ih, b_hh, W_head, b_head, u2y, out, B, K);
}

// round 3
// speedup vs baseline: 1.1174x; 1.1174x over previous
#include <cuda_runtime.h>
#include <math.h>

// KineticsRNN R3: persistent per-CTA recurrence, fp32, f32x2-packed FMA.
// 128 CTAs x 4 batch elements, 384 threads (thread = GRU gate row).
// W_hh in shared (pitch 132, conflict-free LDS.128), W_ih rows in registers.
// Head+RK4 fused into warp 0 (shuffle handoff, no extra barrier).

#define THREADS 384
#define HDIM 128
#define LDIM 32
#define PITCH 132    // W_hh row pitch (words): conflict-free LDS.128
#define HPITCH 132   // sH row pitch (words)

// smem floats: Whh + sH + sLift + sR + sZ + sWhd + sU + sYobs + sYtf
#define SMEM_FLOATS (384*PITCH + 4*HPITCH + 4*LDIM + 4*HDIM + 4*HDIM + 5*132 + 16 + 16 + 16)
#define SMEM_BYTES  (SMEM_FLOATS * 4)

typedef unsigned long long u64;

__device__ __forceinline__ u64 fma2(u64 a, u64 b, u64 c) {
    u64 d;
    asm("fma.rn.f32x2 %0, %1, %2, %3;" : "=l"(d) : "l"(a), "l"(b), "l"(c));
    return d;
}
__device__ __forceinline__ float f2sum(u64 v) {
    float2 f;
    asm("mov.b64 {%0, %1}, %2;" : "=f"(f.x), "=f"(f.y) : "l"(v));
    return f.x + f.y;
}
// fast sigmoid / tanh via MUFU (rel err ~1e-6)
__device__ __forceinline__ float sigm(float x) {
    return __fdividef(1.0f, 1.0f + __expf(-x));
}
__device__ __forceinline__ float tanh_f(float x) {
    return 1.0f - __fdividef(2.0f, __expf(2.0f * x) + 1.0f);
}

__global__ __launch_bounds__(THREADS, 1)
void krnn_kernel(const float* __restrict__ y0,
                 const float* __restrict__ u_seq,
                 const float* __restrict__ dt_seq,
                 const float* __restrict__ y_seq,
                 const float* __restrict__ W_lift,
                 const float* __restrict__ b_lift,
                 const float* __restrict__ W_ih,
                 const float* __restrict__ W_hh,
                 const float* __restrict__ b_ih,
                 const float* __restrict__ b_hh,
                 const float* __restrict__ W_head,
                 const float* __restrict__ b_head,
                 const float* __restrict__ u2y,
                 float* __restrict__ out,
                 int B, int K)
{
    extern __shared__ float sm[];
    float* sWhh  = sm;                       // 384*PITCH
    float* sH    = sWhh + 384 * PITCH;       // 4*HPITCH
    float* sLift = sH + 4 * HPITCH;          // 4*32
    float* sR    = sLift + 4 * LDIM;         // 4*128
    float* sZ    = sR + 4 * HDIM;            // 4*128
    float* sWhd  = sZ + 4 * HDIM;            // 5*132
    float* sU    = sWhd + 5 * 132;           // 4*4
    float* sYobs = sU + 16;                  // 4*4
    float* sYtf  = sYobs + 16;               // 4*4

    const int t   = threadIdx.x;
    const int bg0 = blockIdx.x * 4;

    // ---- stage W_hh (384x128) into padded shared ----
    {
        const float4* src = (const float4*)W_hh;
        for (int idx = t; idx < 384 * (HDIM / 4); idx += THREADS) {
            int row = idx >> 5;
            int cb  = idx & 31;
            *(float4*)(sWhh + row * PITCH + cb * 4) = src[idx];
        }
    }
    // ---- stage W_head (5x128) ----
    for (int idx = t; idx < 5 * HDIM; idx += THREADS) {
        int row = idx / HDIM, c = idx % HDIM;
        sWhd[row * 132 + c] = W_head[idx];
    }

    // ---- W_ih row t in registers as packed f32x2 pairs ----
    u64 wihp[16];
    {
        const ulonglong2* p = (const ulonglong2*)(W_ih + t * LDIM);
#pragma unroll
        for (int i = 0; i < 8; i++) {
            ulonglong2 v = p[i];
            wihp[2 * i] = v.x; wihp[2 * i + 1] = v.y;
        }
    }
    const float bi = b_ih[t];
    const float bh = b_hh[t];

    // ---- lift weights (threads 0..127: row lr, batch lb) ----
    const int lr = t >> 2, lb = t & 3;
    float wl0 = 0, wl1 = 0, wl2 = 0, wl3 = 0, wl4 = 0, wl5 = 0, blf = 0;
    if (t < 128) {
        wl0 = W_lift[lr * 6 + 0]; wl1 = W_lift[lr * 6 + 1]; wl2 = W_lift[lr * 6 + 2];
        wl3 = W_lift[lr * 6 + 3]; wl4 = W_lift[lr * 6 + 4]; wl5 = W_lift[lr * 6 + 5];
        blf = b_lift[lr];
    }

    // ---- warp-0 head/RK4 state ----
    const int hb = t / 5, hp = t % 5;          // valid for t<20
    float bhd = (t < 20) ? b_head[hp] : 0.f;

    float yf0 = 0, yf1 = 0, yf2 = 0, yf3 = 0, yf4 = 0;
    float J00 = 0, J01 = 0, J02 = 0, J10 = 0, J11 = 0, J12 = 0, J20 = 0, J21 = 0, J22 = 0;
    float cu0 = 0, cu1 = 0, cu2 = 0, cdt = 0;
    if (t < 4) {
        int bg = bg0 + t;
        yf0 = y0[bg * 3 + 0]; yf2 = y0[bg * 3 + 1]; yf4 = y0[bg * 3 + 2];
        J00 = u2y[0]; J01 = u2y[1]; J02 = u2y[2];
        J10 = u2y[3]; J11 = u2y[4]; J12 = u2y[5];
        J20 = u2y[6]; J21 = u2y[7]; J22 = u2y[8];
        const float* up = u_seq + (size_t)bg * K * 3;
        cu0 = up[0]; cu1 = up[1]; cu2 = up[2];
        cdt = dt_seq[(size_t)bg * K];
        sU[t * 4 + 0] = cu0; sU[t * 4 + 1] = cu1; sU[t * 4 + 2] = cu2;
        sYobs[t * 4 + 0] = yf0; sYobs[t * 4 + 1] = yf2; sYobs[t * 4 + 2] = yf4;
    }
    for (int i = t; i < 4 * HPITCH; i += THREADS) sH[i] = 0.f;
    __syncthreads();

    const size_t theta_base = (size_t)B * K * 3;

    for (int k = 0; k < K; k++) {
        const bool flag = (k > 0) && (k % 50 == 0);

        // ---- prefetch next-step inputs (warp 0, committed in E phase) ----
        float nu0 = 0, nu1 = 0, nu2 = 0, ndt = 0, nt0 = 0, nt1 = 0, nt2 = 0;
        bool nflag = false;
        if (t < 4 && (k + 1) < K) {
            int bg = bg0 + t;
            const float* up = u_seq + ((size_t)bg * K + (k + 1)) * 3;
            nu0 = up[0]; nu1 = up[1]; nu2 = up[2];
            ndt = dt_seq[(size_t)bg * K + (k + 1)];
            nflag = ((k + 1) % 50) == 0;
            if (nflag) {
                const float* yp = y_seq + ((size_t)bg * K + k) * 3;
                nt0 = yp[0]; nt1 = yp[1]; nt2 = yp[2];
            }
        }

        // ---- lift (t<128) — overlapped with gh below ----
        if (t < 128) {
            const float* ub = sU + lb * 4;
            const float* yb = flag ? (sYtf + lb * 4) : (sYobs + lb * 4);
            float s = blf;
            s = fmaf(wl0, ub[0], s); s = fmaf(wl1, ub[1], s); s = fmaf(wl2, ub[2], s);
            s = fmaf(wl3, yb[0], s); s = fmaf(wl4, yb[1], s); s = fmaf(wl5, yb[2], s);
            sLift[lb * LDIM + lr] = s * sigm(s);
        }

        // ---- gh = W_hh[t,:] @ h[b,:]  (f32x2 packed, no lift dependency) ----
        u64 A0a = 0, A0b = 0, A1a = 0, A1b = 0, A2a = 0, A2b = 0, A3a = 0, A3b = 0;
        {
            const ulonglong2* wr = (const ulonglong2*)(sWhh + t * PITCH);
            const ulonglong2* h0 = (const ulonglong2*)(sH);
            const ulonglong2* h1 = (const ulonglong2*)(sH + HPITCH);
            const ulonglong2* h2 = (const ulonglong2*)(sH + 2 * HPITCH);
            const ulonglong2* h3 = (const ulonglong2*)(sH + 3 * HPITCH);
#pragma unroll
            for (int jb = 0; jb < HDIM / 4; jb++) {
                ulonglong2 w = wr[jb];
                ulonglong2 a = h0[jb];
                A0a = fma2(w.x, a.x, A0a); A0b = fma2(w.y, a.y, A0b);
                ulonglong2 b4 = h1[jb];
                A1a = fma2(w.x, b4.x, A1a); A1b = fma2(w.y, b4.y, A1b);
                ulonglong2 c = h2[jb];
                A2a = fma2(w.x, c.x, A2a); A2b = fma2(w.y, c.y, A2b);
                ulonglong2 d = h3[jb];
                A3a = fma2(w.x, d.x, A3a); A3b = fma2(w.y, d.y, A3b);
            }
        }
        __syncthreads();   // BAR_A: lift visible

        // ---- gx = W_ih[t,:] @ lift[b,:] (weights in regs) ----
        u64 X0a = 0, X0b = 0, X1a = 0, X1b = 0, X2a = 0, X2b = 0, X3a = 0, X3b = 0;
        {
            const ulonglong2* l0 = (const ulonglong2*)(sLift);
            const ulonglong2* l1 = (const ulonglong2*)(sLift + LDIM);
            const ulonglong2* l2 = (const ulonglong2*)(sLift + 2 * LDIM);
            const ulonglong2* l3 = (const ulonglong2*)(sLift + 3 * LDIM);
#pragma unroll
            for (int jb = 0; jb < LDIM / 4; jb++) {
                u64 w0 = wihp[2 * jb], w1 = wihp[2 * jb + 1];
                ulonglong2 a = l0[jb];
                X0a = fma2(w0, a.x, X0a); X0b = fma2(w1, a.y, X0b);
                ulonglong2 b4 = l1[jb];
                X1a = fma2(w0, b4.x, X1a); X1b = fma2(w1, b4.y, X1b);
                ulonglong2 c = l2[jb];
                X2a = fma2(w0, c.x, X2a); X2b = fma2(w1, c.y, X2b);
                ulonglong2 d = l3[jb];
                X3a = fma2(w0, d.x, X3a); X3b = fma2(w1, d.y, X3b);
            }
        }
        float ax0 = f2sum(X0a) + f2sum(X0b);
        float ax1 = f2sum(X1a) + f2sum(X1b);
        float ax2 = f2sum(X2a) + f2sum(X2b);
        float ax3 = f2sum(X3a) + f2sum(X3b);
        float ah0 = f2sum(A0a) + f2sum(A0b);
        float ah1 = f2sum(A1a) + f2sum(A1b);
        float ah2 = f2sum(A2a) + f2sum(A2b);
        float ah3 = f2sum(A3a) + f2sum(A3b);

        float gxn0 = 0, gxn1 = 0, gxn2 = 0, gxn3 = 0;
        float ghn0 = 0, ghn1 = 0, ghn2 = 0, ghn3 = 0;
        if (t < 2 * HDIM) {
            float cst = bi + bh;
            float* base = (t < HDIM) ? sR : sZ;
            int i = (t < HDIM) ? t : (t - HDIM);
            base[0 * HDIM + i] = sigm(ax0 + ah0 + cst);
            base[1 * HDIM + i] = sigm(ax1 + ah1 + cst);
            base[2 * HDIM + i] = sigm(ax2 + ah2 + cst);
            base[3 * HDIM + i] = sigm(ax3 + ah3 + cst);
        } else {
            gxn0 = ax0 + bi; gxn1 = ax1 + bi; gxn2 = ax2 + bi; gxn3 = ax3 + bi;
            ghn0 = ah0 + bh; ghn1 = ah1 + bh; ghn2 = ah2 + bh; ghn3 = ah3 + bh;
        }
        __syncthreads();   // BAR_B: r, z visible

        // ---- h update (threads 256..383) ----
        if (t >= 256) {
            int i = t - 256;
            {
                float r = sR[0 * HDIM + i]; float n = tanh_f(fmaf(r, ghn0, gxn0));
                float z = sZ[0 * HDIM + i]; float ho = sH[0 * HPITCH + i];
                sH[0 * HPITCH + i] = (1.0f - z) * n + z * ho;
            }
            {
                float r = sR[1 * HDIM + i]; float n = tanh_f(fmaf(r, ghn1, gxn1));
                float z = sZ[1 * HDIM + i]; float ho = sH[1 * HPITCH + i];
                sH[1 * HPITCH + i] = (1.0f - z) * n + z * ho;
            }
            {
                float r = sR[2 * HDIM + i]; float n = tanh_f(fmaf(r, ghn2, gxn2));
                float z = sZ[2 * HDIM + i]; float ho = sH[2 * HPITCH + i];
                sH[2 * HPITCH + i] = (1.0f - z) * n + z * ho;
            }
            {
                float r = sR[3 * HDIM + i]; float n = tanh_f(fmaf(r, ghn3, gxn3));
                float z = sZ[3 * HDIM + i]; float ho = sH[3 * HPITCH + i];
                sH[3 * HPITCH + i] = (1.0f - z) * n + z * ho;
            }
        }
        __syncthreads();   // BAR_C: h_new visible

        // ---- warp 0: head + theta + RK4 + buffer rotation (no block barrier inside) ----
        if (t < 32) {
            float thv = 0.f;
            if (t < 20) {
                const ulonglong2* hr = (const ulonglong2*)(sH + hb * HPITCH);
                const ulonglong2* wp = (const ulonglong2*)(sWhd + hp * 132);
                u64 s0 = 0, s1 = 0;
#pragma unroll
                for (int jb = 0; jb < HDIM / 4; jb++) {
                    ulonglong2 h4 = hr[jb];
                    ulonglong2 w4 = wp[jb];
                    s0 = fma2(w4.x, h4.x, s0);
                    s1 = fma2(w4.y, h4.y, s1);
                }
                float s = f2sum(s0) + f2sum(s1) + bhd;
                thv = 0.001f + 1.999f * sigm(s);
                out[theta_base + ((size_t)(bg0 + hb) * K + k) * 5 + hp] = thv;
            }
            // gather 5 thetas to RK4 lanes via shuffle (all 32 lanes participate)
            float th0 = __shfl_sync(0xffffffffu, thv, t * 5 + 0);
            float th1 = __shfl_sync(0xffffffffu, thv, t * 5 + 1);
            float th2 = __shfl_sync(0xffffffffu, thv, t * 5 + 2);
            float th3 = __shfl_sync(0xffffffffu, thv, t * 5 + 3);
            float th4 = __shfl_sync(0xffffffffu, thv, t * 5 + 4);

            if (t < 4) {
                // y_jump
                yf0 += cu0 * J00 + cu1 * J10 + cu2 * J20;
                yf2 += cu0 * J01 + cu1 * J11 + cu2 * J21;
                yf4 += cu0 * J02 + cu1 * J12 + cu2 * J22;

                float h  = cdt;
                float hhf = 0.5f * h;
#define RHS(A_, Bv, C_, D_, E_, d0, d1, d2, d3, d4)                      \
                {                                                        \
                    float r1 = th0 * (A_) * (Bv);                        \
                    float r2 = th1 * (C_);                               \
                    float r3 = th2 * (C_) * (D_);                        \
                    float r4 = th3 * (E_);                               \
                    float r5 = th4 * (A_);                               \
                    d0 = -r1 - r5; d1 = -r1 + r2; d2 = r1 - r2 - r3;     \
                    d3 = -r3 + r4; d4 = r3 - r4 + r5;                    \
                }
                float a0, a1, a2, a3, a4;
                RHS(yf0, yf1, yf2, yf3, yf4, a0, a1, a2, a3, a4);
                float t0 = yf0 + hhf * a0, t1 = yf1 + hhf * a1, t2 = yf2 + hhf * a2,
                      t3 = yf3 + hhf * a3, t4 = yf4 + hhf * a4;
                float b0, b1, b2, b3, b4v;
                RHS(t0, t1, t2, t3, t4, b0, b1, b2, b3, b4v);
                t0 = yf0 + hhf * b0; t1 = yf1 + hhf * b1; t2 = yf2 + hhf * b2;
                t3 = yf3 + hhf * b3; t4 = yf4 + hhf * b4v;
                float c0, c1, c2, c3, c4;
                RHS(t0, t1, t2, t3, t4, c0, c1, c2, c3, c4);
                t0 = yf0 + h * c0; t1 = yf1 + h * c1; t2 = yf2 + h * c2;
                t3 = yf3 + h * c3; t4 = yf4 + h * c4;
                float d0, d1, d2, d3, d4;
                RHS(t0, t1, t2, t3, t4, d0, d1, d2, d3, d4);
#undef RHS
                float s6 = h * (1.0f / 6.0f);
                yf0 = fmaxf(yf0 + s6 * (a0 + 2.f * b0 + 2.f * c0 + d0), 0.f);
                yf1 = fmaxf(yf1 + s6 * (a1 + 2.f * b1 + 2.f * c1 + d1), 0.f);
                yf2 = fmaxf(yf2 + s6 * (a2 + 2.f * b2 + 2.f * c2 + d2), 0.f);
                yf3 = fmaxf(yf3 + s6 * (a3 + 2.f * b3 + 2.f * c3 + d3), 0.f);
                yf4 = fmaxf(yf4 + s6 * (a4 + 2.f * b4v + 2.f * c4 + d4), 0.f);

                int bg = bg0 + t;
                float* yo = out + ((size_t)bg * K + k) * 3;
                yo[0] = yf0; yo[1] = yf2; yo[2] = yf4;
                sYobs[t * 4 + 0] = yf0; sYobs[t * 4 + 1] = yf2; sYobs[t * 4 + 2] = yf4;

                if (k + 1 < K) {
                    sU[t * 4 + 0] = nu0; sU[t * 4 + 1] = nu1; sU[t * 4 + 2] = nu2;
                    if (nflag) { sYtf[t * 4 + 0] = nt0; sYtf[t * 4 + 1] = nt1; sYtf[t * 4 + 2] = nt2; }
                    cu0 = nu0; cu1 = nu1; cu2 = nu2; cdt = ndt;
                }
            }
        }
        __syncthreads();   // BAR_E: sU/sYobs/sYtf visible for next lift
    }
}

extern "C" void kernel_launch(void* const* d_in, const int* in_sizes, int n_in,
                              void* d_out, int out_size)
{
    const float* y0     = (const float*)d_in[0];
    const float* u_seq  = (const float*)d_in[1];
    const float* dt_seq = (const float*)d_in[2];
    const float* y_seq  = (const float*)d_in[3];
    const float* W_lift = (const float*)d_in[4];
    const float* b_lift = (const float*)d_in[5];
    const float* W_ih   = (const float*)d_in[6];
    const float* W_hh   = (const float*)d_in[7];
    const float* b_ih   = (const float*)d_in[8];
    const float* b_hh   = (const float*)d_in[9];
    const float* W_head = (const float*)d_in[10];
    const float* b_head = (const float*)d_in[11];
    const float* u2y    = (const float*)d_in[12];
    float* out = (float*)d_out;

    int B = in_sizes[0] / 3;
    int K = in_sizes[2] / B;

    cudaFuncSetAttribute(krnn_kernel, cudaFuncAttributeMaxDynamicSharedMemorySize, SMEM_BYTES);
    krnn_kernel<<<B / 4, THREADS, SMEM_BYTES>>>(
        y0, u_seq, dt_seq, y_seq, W_lift, b_lift, W_ih, W_hh,
        b_ih, b_hh, W_head, b_head, u2y, out, B, K);
}

// round 4
// speedup vs baseline: 1.3661x; 1.2226x over previous
#include <cuda_runtime.h>
#include <math.h>

// KineticsRNN R4: persistent per-CTA recurrence, fp32, f32x2 FMA.
// 128 CTAs x 4 batch, 384 threads. Thread t = (row-pair p=t>>1, K-half c=t&1):
// 2 rows x half-K per thread, shfl.bfly(1) reduction -> thread t owns row t.
// Chunk-gap smem layouts keep all mainloop LDS conflict-free.

#define THREADS 384
#define HDIM 128
#define LDIM 32
#define PITCH 132     // W_hh / sH / sWhd row pitch (words); chunk1 at +68
#define CGAP 68       // K-chunk-1 word offset within a row
#define LPITCH 36     // sLift row pitch; chunk1 at +20
#define LGAP 20

#define SMEM_FLOATS (384*PITCH + 4*PITCH + 4*LPITCH + 4*HDIM + 4*HDIM + 5*PITCH + 16 + 16 + 16)
#define SMEM_BYTES  (SMEM_FLOATS * 4)

typedef unsigned long long u64;

__device__ __forceinline__ u64 fma2(u64 a, u64 b, u64 c) {
    u64 d;
    asm("fma.rn.f32x2 %0, %1, %2, %3;" : "=l"(d) : "l"(a), "l"(b), "l"(c));
    return d;
}
__device__ __forceinline__ float f2sum(u64 v) {
    float2 f;
    asm("mov.b64 {%0, %1}, %2;" : "=f"(f.x), "=f"(f.y) : "l"(v));
    return f.x + f.y;
}
__device__ __forceinline__ float sigm(float x) {
    return __fdividef(1.0f, 1.0f + __expf(-x));
}
__device__ __forceinline__ float tanh_f(float x) {
    return 1.0f - __fdividef(2.0f, __expf(2.0f * x) + 1.0f);
}

__global__ __launch_bounds__(THREADS, 1)
void krnn_kernel(const float* __restrict__ y0,
                 const float* __restrict__ u_seq,
                 const float* __restrict__ dt_seq,
                 const float* __restrict__ y_seq,
                 const float* __restrict__ W_lift,
                 const float* __restrict__ b_lift,
                 const float* __restrict__ W_ih,
                 const float* __restrict__ W_hh,
                 const float* __restrict__ b_ih,
                 const float* __restrict__ b_hh,
                 const float* __restrict__ W_head,
                 const float* __restrict__ b_head,
                 const float* __restrict__ u2y,
                 float* __restrict__ out,
                 int B, int K)
{
    extern __shared__ float sm[];
    float* sWhh  = sm;                       // 384*132 (gapped rows)
    float* sH    = sWhh + 384 * PITCH;       // 4*132 (gapped)
    float* sLift = sH + 4 * PITCH;           // 4*36 (gapped)
    float* sR    = sLift + 4 * LPITCH;       // 4*128
    float* sZ    = sR + 4 * HDIM;            // 4*128
    float* sWhd  = sZ + 4 * HDIM;            // 5*132 (contiguous 128 + pad)
    float* sU    = sWhd + 5 * PITCH;         // 4*4
    float* sYobs = sU + 16;                  // 4*4
    float* sYtf  = sYobs + 16;               // 4*4

    const int t   = threadIdx.x;
    const int bg0 = blockIdx.x * 4;
    const int c   = t & 1;          // K-half
    const int r0  = t & ~1;         // first row of this thread's pair

    // ---- stage W_hh (384x128) into gapped shared: word(row,k) = row*132 + k + 4*(k>=64) ----
    {
        const float4* src = (const float4*)W_hh;
        for (int idx = t; idx < 384 * (HDIM / 4); idx += THREADS) {
            int row = idx >> 5;
            int kb  = idx & 31;
            int dst = row * PITCH + 4 * kb + ((kb >> 4) << 2);
            *(float4*)(sWhh + dst) = src[idx];
        }
    }
    // ---- stage W_head (5x128), contiguous ----
    for (int idx = t; idx < 5 * HDIM; idx += THREADS) {
        int row = idx / HDIM, cc = idx % HDIM;
        sWhd[row * PITCH + cc] = W_head[idx];
    }

    // ---- W_ih: rows r0, r0+1, K-chunk c (16 floats each) in regs as f32x2 pairs ----
    u64 wih0[8], wih1[8];
    {
        const ulonglong2* p0 = (const ulonglong2*)(W_ih + r0 * LDIM + 16 * c);
        const ulonglong2* p1 = (const ulonglong2*)(W_ih + (r0 + 1) * LDIM + 16 * c);
#pragma unroll
        for (int i = 0; i < 4; i++) {
            ulonglong2 v0 = p0[i]; wih0[2 * i] = v0.x; wih0[2 * i + 1] = v0.y;
            ulonglong2 v1 = p1[i]; wih1[2 * i] = v1.x; wih1[2 * i + 1] = v1.y;
        }
    }
    const float bi = b_ih[t];
    const float bh = b_hh[t];

    // ---- lift weights (threads 0..127: row lr, batch lb) ----
    const int lr = t >> 2, lb = t & 3;
    float wl0 = 0, wl1 = 0, wl2 = 0, wl3 = 0, wl4 = 0, wl5 = 0, blf = 0;
    if (t < 128) {
        wl0 = W_lift[lr * 6 + 0]; wl1 = W_lift[lr * 6 + 1]; wl2 = W_lift[lr * 6 + 2];
        wl3 = W_lift[lr * 6 + 3]; wl4 = W_lift[lr * 6 + 4]; wl5 = W_lift[lr * 6 + 5];
        blf = b_lift[lr];
    }
    const int lgl = lr + ((lr >> 4) << 2);   // gapped lift index

    // ---- warp-0 head/RK4 state ----
    const int hb = t / 5, hp = t % 5;        // valid for t<20
    float bhd = (t < 20) ? b_head[hp] : 0.f;

    float yf0 = 0, yf1 = 0, yf2 = 0, yf3 = 0, yf4 = 0;
    float J00 = 0, J01 = 0, J02 = 0, J10 = 0, J11 = 0, J12 = 0, J20 = 0, J21 = 0, J22 = 0;
    float cu0 = 0, cu1 = 0, cu2 = 0, cdt = 0;
    if (t < 4) {
        int bg = bg0 + t;
        yf0 = y0[bg * 3 + 0]; yf2 = y0[bg * 3 + 1]; yf4 = y0[bg * 3 + 2];
        J00 = u2y[0]; J01 = u2y[1]; J02 = u2y[2];
        J10 = u2y[3]; J11 = u2y[4]; J12 = u2y[5];
        J20 = u2y[6]; J21 = u2y[7]; J22 = u2y[8];
        const float* up = u_seq + (size_t)bg * K * 3;
        cu0 = up[0]; cu1 = up[1]; cu2 = up[2];
        cdt = dt_seq[(size_t)bg * K];
        sU[t * 4 + 0] = cu0; sU[t * 4 + 1] = cu1; sU[t * 4 + 2] = cu2;
        sYobs[t * 4 + 0] = yf0; sYobs[t * 4 + 1] = yf2; sYobs[t * 4 + 2] = yf4;
    }
    for (int i = t; i < 4 * PITCH; i += THREADS) sH[i] = 0.f;
    for (int i = t; i < 4 * LPITCH; i += THREADS) sLift[i] = 0.f;
    __syncthreads();

    const size_t theta_base = (size_t)B * K * 3;

    for (int k = 0; k < K; k++) {
        const bool flag = (k > 0) && (k % 50 == 0);

        // ---- prefetch next-step inputs ----
        float nu0 = 0, nu1 = 0, nu2 = 0, ndt = 0, nt0 = 0, nt1 = 0, nt2 = 0;
        bool nflag = false;
        if (t < 4 && (k + 1) < K) {
            int bg = bg0 + t;
            const float* up = u_seq + ((size_t)bg * K + (k + 1)) * 3;
            nu0 = up[0]; nu1 = up[1]; nu2 = up[2];
            ndt = dt_seq[(size_t)bg * K + (k + 1)];
            nflag = ((k + 1) % 50) == 0;
            if (nflag) {
                const float* yp = y_seq + ((size_t)bg * K + k) * 3;
                nt0 = yp[0]; nt1 = yp[1]; nt2 = yp[2];
            }
        }

        // ---- lift (t<128), overlapped with gh ----
        if (t < 128) {
            const float* ub = sU + lb * 4;
            const float* yb = flag ? (sYtf + lb * 4) : (sYobs + lb * 4);
            float s = blf;
            s = fmaf(wl0, ub[0], s); s = fmaf(wl1, ub[1], s); s = fmaf(wl2, ub[2], s);
            s = fmaf(wl3, yb[0], s); s = fmaf(wl4, yb[1], s); s = fmaf(wl5, yb[2], s);
            sLift[lb * LPITCH + lgl] = s * sigm(s);
        }

        // ---- gh: rows r0,r0+1 x K-half c x 4 batches (f32x2, 1 acc per row-batch) ----
        u64 g00 = 0, g01 = 0, g02 = 0, g03 = 0;   // row r0, batches 0..3
        u64 g10 = 0, g11 = 0, g12 = 0, g13 = 0;   // row r0+1
        {
            const ulonglong2* w0 = (const ulonglong2*)(sWhh + r0 * PITCH + CGAP * c);
            const ulonglong2* w1 = (const ulonglong2*)(sWhh + (r0 + 1) * PITCH + CGAP * c);
            const ulonglong2* x0 = (const ulonglong2*)(sH + 0 * PITCH + CGAP * c);
            const ulonglong2* x1 = (const ulonglong2*)(sH + 1 * PITCH + CGAP * c);
            const ulonglong2* x2 = (const ulonglong2*)(sH + 2 * PITCH + CGAP * c);
            const ulonglong2* x3 = (const ulonglong2*)(sH + 3 * PITCH + CGAP * c);
#pragma unroll
            for (int j = 0; j < 16; j++) {
                ulonglong2 a = w0[j];
                ulonglong2 b4 = w1[j];
                ulonglong2 v0 = x0[j];
                g00 = fma2(a.x, v0.x, g00); g00 = fma2(a.y, v0.y, g00);
                g10 = fma2(b4.x, v0.x, g10); g10 = fma2(b4.y, v0.y, g10);
                ulonglong2 v1 = x1[j];
                g01 = fma2(a.x, v1.x, g01); g01 = fma2(a.y, v1.y, g01);
                g11 = fma2(b4.x, v1.x, g11); g11 = fma2(b4.y, v1.y, g11);
                ulonglong2 v2 = x2[j];
                g02 = fma2(a.x, v2.x, g02); g02 = fma2(a.y, v2.y, g02);
                g12 = fma2(b4.x, v2.x, g12); g12 = fma2(b4.y, v2.y, g12);
                ulonglong2 v3 = x3[j];
                g03 = fma2(a.x, v3.x, g03); g03 = fma2(a.y, v3.y, g03);
                g13 = fma2(b4.x, v3.x, g13); g13 = fma2(b4.y, v3.y, g13);
            }
        }
        __syncthreads();   // BAR_A: lift visible

        // ---- gx: W_ih rows r0,r0+1 chunk c (regs) x lift ----
        u64 q00 = 0, q01 = 0, q02 = 0, q03 = 0;
        u64 q10 = 0, q11 = 0, q12 = 0, q13 = 0;
        {
            const ulonglong2* l0 = (const ulonglong2*)(sLift + 0 * LPITCH + LGAP * c);
            const ulonglong2* l1 = (const ulonglong2*)(sLift + 1 * LPITCH + LGAP * c);
            const ulonglong2* l2 = (const ulonglong2*)(sLift + 2 * LPITCH + LGAP * c);
            const ulonglong2* l3 = (const ulonglong2*)(sLift + 3 * LPITCH + LGAP * c);
#pragma unroll
            for (int j = 0; j < 4; j++) {
                u64 wa0 = wih0[2 * j], wb0 = wih0[2 * j + 1];
                u64 wa1 = wih1[2 * j], wb1 = wih1[2 * j + 1];
                ulonglong2 v0 = l0[j];
                q00 = fma2(wa0, v0.x, q00); q00 = fma2(wb0, v0.y, q00);
                q10 = fma2(wa1, v0.x, q10); q10 = fma2(wb1, v0.y, q10);
                ulonglong2 v1 = l1[j];
                q01 = fma2(wa0, v1.x, q01); q01 = fma2(wb0, v1.y, q01);
                q11 = fma2(wa1, v1.x, q11); q11 = fma2(wb1, v1.y, q11);
                ulonglong2 v2 = l2[j];
                q02 = fma2(wa0, v2.x, q02); q02 = fma2(wb0, v2.y, q02);
                q12 = fma2(wa1, v2.x, q12); q12 = fma2(wb1, v2.y, q12);
                ulonglong2 v3 = l3[j];
                q03 = fma2(wa0, v3.x, q03); q03 = fma2(wb0, v3.y, q03);
                q13 = fma2(wa1, v3.x, q13); q13 = fma2(wb1, v3.y, q13);
            }
        }

        // ---- reduce K-halves across lane pairs (bfly ^1), pick row = t ----
        float gxn0 = 0, gxn1 = 0, gxn2 = 0, gxn3 = 0;
        float ghn0 = 0, ghn1 = 0, ghn2 = 0, ghn3 = 0;
        if (t < 2 * HDIM) {
            // r/z rows: gx+gh merge before reduction (8 shfl)
            float s00 = f2sum(g00) + f2sum(q00), s01 = f2sum(g01) + f2sum(q01);
            float s02 = f2sum(g02) + f2sum(q02), s03 = f2sum(g03) + f2sum(q03);
            float s10 = f2sum(g10) + f2sum(q10), s11 = f2sum(g11) + f2sum(q11);
            float s12 = f2sum(g12) + f2sum(q12), s13 = f2sum(g13) + f2sum(q13);
            s00 += __shfl_xor_sync(0xffffffffu, s00, 1);
            s01 += __shfl_xor_sync(0xffffffffu, s01, 1);
            s02 += __shfl_xor_sync(0xffffffffu, s02, 1);
            s03 += __shfl_xor_sync(0xffffffffu, s03, 1);
            s10 += __shfl_xor_sync(0xffffffffu, s10, 1);
            s11 += __shfl_xor_sync(0xffffffffu, s11, 1);
            s12 += __shfl_xor_sync(0xffffffffu, s12, 1);
            s13 += __shfl_xor_sync(0xffffffffu, s13, 1);
            float a0 = c ? s10 : s00, a1 = c ? s11 : s01;
            float a2 = c ? s12 : s02, a3 = c ? s13 : s03;
            float cst = bi + bh;
            float* base = (t < HDIM) ? sR : sZ;
            int i = (t < HDIM) ? t : (t - HDIM);
            base[0 * HDIM + i] = sigm(a0 + cst);
            base[1 * HDIM + i] = sigm(a1 + cst);
            base[2 * HDIM + i] = sigm(a2 + cst);
            base[3 * HDIM + i] = sigm(a3 + cst);
        } else {
            // n rows: keep gx / gh separate (16 shfl)
            float x00 = f2sum(q00), x01 = f2sum(q01), x02 = f2sum(q02), x03 = f2sum(q03);
            float x10 = f2sum(q10), x11 = f2sum(q11), x12 = f2sum(q12), x13 = f2sum(q13);
            float h00 = f2sum(g00), h01 = f2sum(g01), h02 = f2sum(g02), h03 = f2sum(g03);
            float h10 = f2sum(g10), h11 = f2sum(g11), h12 = f2sum(g12), h13 = f2sum(g13);
            x00 += __shfl_xor_sync(0xffffffffu, x00, 1);
            x01 += __shfl_xor_sync(0xffffffffu, x01, 1);
            x02 += __shfl_xor_sync(0xffffffffu, x02, 1);
            x03 += __shfl_xor_sync(0xffffffffu, x03, 1);
            x10 += __shfl_xor_sync(0xffffffffu, x10, 1);
            x11 += __shfl_xor_sync(0xffffffffu, x11, 1);
            x12 += __shfl_xor_sync(0xffffffffu, x12, 1);
            x13 += __shfl_xor_sync(0xffffffffu, x13, 1);
            h00 += __shfl_xor_sync(0xffffffffu, h00, 1);
            h01 += __shfl_xor_sync(0xffffffffu, h01, 1);
            h02 += __shfl_xor_sync(0xffffffffu, h02, 1);
            h03 += __shfl_xor_sync(0xffffffffu, h03, 1);
            h10 += __shfl_xor_sync(0xffffffffu, h10, 1);
            h11 += __shfl_xor_sync(0xffffffffu, h11, 1);
            h12 += __shfl_xor_sync(0xffffffffu, h12, 1);
            h13 += __shfl_xor_sync(0xffffffffu, h13, 1);
            gxn0 = (c ? x10 : x00) + bi; gxn1 = (c ? x11 : x01) + bi;
            gxn2 = (c ? x12 : x02) + bi; gxn3 = (c ? x13 : x03) + bi;
            ghn0 = (c ? h10 : h00) + bh; ghn1 = (c ? h11 : h01) + bh;
            ghn2 = (c ? h12 : h02) + bh; ghn3 = (c ? h13 : h03) + bh;
        }
        __syncthreads();   // BAR_B: r, z visible

        // ---- h update (threads 256..383, hidden i), gapped sH ----
        if (t >= 256) {
            int i = t - 256;
            int gi = i + ((i >> 6) << 2);
            {
                float r = sR[0 * HDIM + i]; float n = tanh_f(fmaf(r, ghn0, gxn0));
                float z = sZ[0 * HDIM + i]; float ho = sH[0 * PITCH + gi];
                sH[0 * PITCH + gi] = (1.0f - z) * n + z * ho;
            }
            {
                float r = sR[1 * HDIM + i]; float n = tanh_f(fmaf(r, ghn1, gxn1));
                float z = sZ[1 * HDIM + i]; float ho = sH[1 * PITCH + gi];
                sH[1 * PITCH + gi] = (1.0f - z) * n + z * ho;
            }
            {
                float r = sR[2 * HDIM + i]; float n = tanh_f(fmaf(r, ghn2, gxn2));
                float z = sZ[2 * HDIM + i]; float ho = sH[2 * PITCH + gi];
                sH[2 * PITCH + gi] = (1.0f - z) * n + z * ho;
            }
            {
                float r = sR[3 * HDIM + i]; float n = tanh_f(fmaf(r, ghn3, gxn3));
                float z = sZ[3 * HDIM + i]; float ho = sH[3 * PITCH + gi];
                sH[3 * PITCH + gi] = (1.0f - z) * n + z * ho;
            }
        }
        __syncthreads();   // BAR_C: h_new visible

        // ---- warp 0: head + theta + RK4 + buffer rotation ----
        if (t < 32) {
            float thv = 0.f;
            if (t < 20) {
                u64 s0 = 0, s1 = 0;
#pragma unroll
                for (int half = 0; half < 2; half++) {
                    const ulonglong2* hr = (const ulonglong2*)(sH + hb * PITCH + CGAP * half);
                    const ulonglong2* wp = (const ulonglong2*)(sWhd + hp * PITCH + 64 * half);
#pragma unroll
                    for (int jb = 0; jb < 16; jb++) {
                        ulonglong2 h4 = hr[jb];
                        ulonglong2 w4 = wp[jb];
                        s0 = fma2(w4.x, h4.x, s0);
                        s1 = fma2(w4.y, h4.y, s1);
                    }
                }
                float s = f2sum(s0) + f2sum(s1) + bhd;
                thv = 0.001f + 1.999f * sigm(s);
                out[theta_base + ((size_t)(bg0 + hb) * K + k) * 5 + hp] = thv;
            }
            float th0 = __shfl_sync(0xffffffffu, thv, t * 5 + 0);
            float th1 = __shfl_sync(0xffffffffu, thv, t * 5 + 1);
            float th2 = __shfl_sync(0xffffffffu, thv, t * 5 + 2);
            float th3 = __shfl_sync(0xffffffffu, thv, t * 5 + 3);
            float th4 = __shfl_sync(0xffffffffu, thv, t * 5 + 4);

            if (t < 4) {
                yf0 += cu0 * J00 + cu1 * J10 + cu2 * J20;
                yf2 += cu0 * J01 + cu1 * J11 + cu2 * J21;
                yf4 += cu0 * J02 + cu1 * J12 + cu2 * J22;

                float h  = cdt;
                float hhf = 0.5f * h;
#define RHS(A_, Bv, C_, D_, E_, d0, d1, d2, d3, d4)                      \
                {                                                        \
                    float r1 = th0 * (A_) * (Bv);                        \
                    float r2 = th1 * (C_);                               \
                    float r3 = th2 * (C_) * (D_);                        \
                    float r4 = th3 * (E_);                               \
                    float r5 = th4 * (A_);                               \
                    d0 = -r1 - r5; d1 = -r1 + r2; d2 = r1 - r2 - r3;     \
                    d3 = -r3 + r4; d4 = r3 - r4 + r5;                    \
                }
                float a0, a1, a2, a3, a4;
                RHS(yf0, yf1, yf2, yf3, yf4, a0, a1, a2, a3, a4);
                float t0 = yf0 + hhf * a0, t1 = yf1 + hhf * a1, t2 = yf2 + hhf * a2,
                      t3 = yf3 + hhf * a3, t4 = yf4 + hhf * a4;
                float b0, b1, b2, b3, b4v;
                RHS(t0, t1, t2, t3, t4, b0, b1, b2, b3, b4v);
                t0 = yf0 + hhf * b0; t1 = yf1 + hhf * b1; t2 = yf2 + hhf * b2;
                t3 = yf3 + hhf * b3; t4 = yf4 + hhf * b4v;
                float c0, c1, c2, c3, c4;
                RHS(t0, t1, t2, t3, t4, c0, c1, c2, c3, c4);
                t0 = yf0 + h * c0; t1 = yf1 + h * c1; t2 = yf2 + h * c2;
                t3 = yf3 + h * c3; t4 = yf4 + h * c4;
                float d0, d1, d2, d3, d4;
                RHS(t0, t1, t2, t3, t4, d0, d1, d2, d3, d4);
#undef RHS
                float s6 = h * (1.0f / 6.0f);
                yf0 = fmaxf(yf0 + s6 * (a0 + 2.f * b0 + 2.f * c0 + d0), 0.f);
                yf1 = fmaxf(yf1 + s6 * (a1 + 2.f * b1 + 2.f * c1 + d1), 0.f);
                yf2 = fmaxf(yf2 + s6 * (a2 + 2.f * b2 + 2.f * c2 + d2), 0.f);
                yf3 = fmaxf(yf3 + s6 * (a3 + 2.f * b3 + 2.f * c3 + d3), 0.f);
                yf4 = fmaxf(yf4 + s6 * (a4 + 2.f * b4v + 2.f * c4 + d4), 0.f);

                int bg = bg0 + t;
                float* yo = out + ((size_t)bg * K + k) * 3;
                yo[0] = yf0; yo[1] = yf2; yo[2] = yf4;
                sYobs[t * 4 + 0] = yf0; sYobs[t * 4 + 1] = yf2; sYobs[t * 4 + 2] = yf4;

                if (k + 1 < K) {
                    sU[t * 4 + 0] = nu0; sU[t * 4 + 1] = nu1; sU[t * 4 + 2] = nu2;
                    if (nflag) { sYtf[t * 4 + 0] = nt0; sYtf[t * 4 + 1] = nt1; sYtf[t * 4 + 2] = nt2; }
                    cu0 = nu0; cu1 = nu1; cu2 = nu2; cdt = ndt;
                }
            }
        }
        __syncthreads();   // BAR_E
    }
}

extern "C" void kernel_launch(void* const* d_in, const int* in_sizes, int n_in,
                              void* d_out, int out_size)
{
    const float* y0     = (const float*)d_in[0];
    const float* u_seq  = (const float*)d_in[1];
    const float* dt_seq = (const float*)d_in[2];
    const float* y_seq  = (const float*)d_in[3];
    const float* W_lift = (const float*)d_in[4];
    const float* b_lift = (const float*)d_in[5];
    const float* W_ih   = (const float*)d_in[6];
    const float* W_hh   = (const float*)d_in[7];
    const float* b_ih   = (const float*)d_in[8];
    const float* b_hh   = (const float*)d_in[9];
    const float* W_head = (const float*)d_in[10];
    const float* b_head = (const float*)d_in[11];
    const float* u2y    = (const float*)d_in[12];
    float* out = (float*)d_out;

    int B = in_sizes[0] / 3;
    int K = in_sizes[2] / B;

    cudaFuncSetAttribute(krnn_kernel, cudaFuncAttributeMaxDynamicSharedMemorySize, SMEM_BYTES);
    krnn_kernel<<<B / 4, THREADS, SMEM_BYTES>>>(
        y0, u_seq, dt_seq, y_seq, W_lift, b_lift, W_ih, W_hh,
        b_ih, b_hh, W_head, b_head, u2y, out, B, K);
}

// round 5
// speedup vs baseline: 1.7143x; 1.2549x over previous
#include <cuda_runtime.h>
#include <math.h>

// KineticsRNN R5: warp-specialized persistent recurrence, fp32 f32x2.
// 128 CTAs x 4 batch. 256 "mat" threads: thread (i=t>>1, c=t&1) owns gate rows
// (r_i, z_i, n_i) for K-half c -> shfl.bfly(1) gives full gates, h_new computed
// locally (no cross-thread gate handoff). 128 "aux" threads run head+RK4+lift
// overlapped with the mat warps' gh of the next step. 2 full barriers/step.

#define THREADS 384
#define MATT 256
#define HDIM 128
#define PITCH 136     // W_hh / sH / sWhd row pitch (words); K-chunk1 at +68
#define CGAP 68
#define LPITCH 40     // sLift row pitch; chunk1 at +20
#define LGAP 20

#define SMEM_FLOATS (384*PITCH + 4*PITCH + 4*LPITCH + 5*PITCH + 16 + 16 + 16)
#define SMEM_BYTES  (SMEM_FLOATS * 4)

typedef unsigned long long u64;

__device__ __forceinline__ u64 fma2(u64 a, u64 b, u64 c) {
    u64 d;
    asm("fma.rn.f32x2 %0, %1, %2, %3;" : "=l"(d) : "l"(a), "l"(b), "l"(c));
    return d;
}
__device__ __forceinline__ float f2sum(u64 v) {
    float2 f;
    asm("mov.b64 {%0, %1}, %2;" : "=f"(f.x), "=f"(f.y) : "l"(v));
    return f.x + f.y;
}
__device__ __forceinline__ float sigm(float x) {
    return __fdividef(1.0f, 1.0f + __expf(-x));
}
__device__ __forceinline__ float tanh_f(float x) {
    return 1.0f - __fdividef(2.0f, __expf(2.0f * x) + 1.0f);
}

__global__ __launch_bounds__(THREADS, 1)
void krnn_kernel(const float* __restrict__ y0,
                 const float* __restrict__ u_seq,
                 const float* __restrict__ dt_seq,
                 const float* __restrict__ y_seq,
                 const float* __restrict__ W_lift,
                 const float* __restrict__ b_lift,
                 const float* __restrict__ W_ih,
                 const float* __restrict__ W_hh,
                 const float* __restrict__ b_ih,
                 const float* __restrict__ b_hh,
                 const float* __restrict__ W_head,
                 const float* __restrict__ b_head,
                 const float* __restrict__ u2y,
                 float* __restrict__ out,
                 int B, int K)
{
    extern __shared__ float sm[];
    float* sWhh  = sm;                       // 384*136 (gapped rows)
    float* sH    = sWhh + 384 * PITCH;       // 4*136 (gapped)
    float* sLift = sH + 4 * PITCH;           // 4*40 (gapped)
    float* sWhd  = sLift + 4 * LPITCH;       // 5*136
    float* sU    = sWhd + 5 * PITCH;         // 4*4
    float* sYobs = sU + 16;                  // 4*4
    float* sYtf  = sYobs + 16;               // 4*4

    const int t   = threadIdx.x;
    const int bg0 = blockIdx.x * 4;

    // ---- stage W_hh gapped: word(row,k) = row*136 + k + 4*(k>=64) ----
    {
        const float4* src = (const float4*)W_hh;
        for (int idx = t; idx < 384 * 32; idx += THREADS) {
            int row = idx >> 5, kb = idx & 31;
            int dst = row * PITCH + 4 * kb + ((kb >> 4) << 2);
            *(float4*)(sWhh + dst) = src[idx];
        }
    }
    for (int idx = t; idx < 5 * HDIM; idx += THREADS)
        sWhd[(idx / HDIM) * PITCH + (idx % HDIM)] = W_head[idx];

    // ================= mat-thread persistent state =================
    const int i = t >> 1, c = t & 1;
    u64 wr_[8], wz_[8], wn_[8];
    float cr = 0, cz = 0, bxn = 0, bhn = 0;
    if (t < MATT) {
        const ulonglong2* pr = (const ulonglong2*)(W_ih + (size_t)i * 32 + 16 * c);
        const ulonglong2* pz = (const ulonglong2*)(W_ih + (size_t)(128 + i) * 32 + 16 * c);
        const ulonglong2* pn = (const ulonglong2*)(W_ih + (size_t)(256 + i) * 32 + 16 * c);
#pragma unroll
        for (int j = 0; j < 4; j++) {
            ulonglong2 vr = pr[j]; wr_[2 * j] = vr.x; wr_[2 * j + 1] = vr.y;
            ulonglong2 vz = pz[j]; wz_[2 * j] = vz.x; wz_[2 * j + 1] = vz.y;
            ulonglong2 vn = pn[j]; wn_[2 * j] = vn.x; wn_[2 * j + 1] = vn.y;
        }
        cr  = b_ih[i] + b_hh[i];
        cz  = b_ih[128 + i] + b_hh[128 + i];
        bxn = b_ih[256 + i];
        bhn = b_hh[256 + i];
    }

    // ================= aux-thread persistent state =================
    const int g   = t - 256;                  // aux index (valid t>=256)
    const int hbh = g / 5, hph = g % 5;       // head mapping (g<20)
    const int lr  = g >> 2, lbb = g & 3;      // lift mapping
    const int lgl = lr + ((lr >> 4) << 2);
    float bhd = 0.f;
    float wl0 = 0, wl1 = 0, wl2 = 0, wl3 = 0, wl4 = 0, wl5 = 0, blf = 0;
    float yf0 = 0, yf1 = 0, yf2 = 0, yf3 = 0, yf4 = 0;
    float J00 = 0, J01 = 0, J02 = 0, J10 = 0, J11 = 0, J12 = 0, J20 = 0, J21 = 0, J22 = 0;
    float cu0 = 0, cu1 = 0, cu2 = 0, cdt = 0;
    if (t >= MATT) {
        if (g < 20) bhd = b_head[hph];
        wl0 = W_lift[lr * 6 + 0]; wl1 = W_lift[lr * 6 + 1]; wl2 = W_lift[lr * 6 + 2];
        wl3 = W_lift[lr * 6 + 3]; wl4 = W_lift[lr * 6 + 4]; wl5 = W_lift[lr * 6 + 5];
        blf = b_lift[lr];
        if (g < 4) {
            int bg = bg0 + g;
            yf0 = y0[bg * 3 + 0]; yf2 = y0[bg * 3 + 1]; yf4 = y0[bg * 3 + 2];
            J00 = u2y[0]; J01 = u2y[1]; J02 = u2y[2];
            J10 = u2y[3]; J11 = u2y[4]; J12 = u2y[5];
            J20 = u2y[6]; J21 = u2y[7]; J22 = u2y[8];
            const float* up = u_seq + (size_t)bg * K * 3;
            cu0 = up[0]; cu1 = up[1]; cu2 = up[2];
            cdt = dt_seq[(size_t)bg * K];
            sU[g * 4 + 0] = cu0; sU[g * 4 + 1] = cu1; sU[g * 4 + 2] = cu2;
            sYobs[g * 4 + 0] = yf0; sYobs[g * 4 + 1] = yf2; sYobs[g * 4 + 2] = yf4;
        }
    }
    for (int idx = t; idx < 4 * PITCH; idx += THREADS) sH[idx] = 0.f;
    __syncthreads();

    // ---- prologue: lift(0) ----
    if (t >= MATT) {
        const float* ub = sU + lbb * 4;
        const float* yb = sYobs + lbb * 4;
        float s = blf;
        s = fmaf(wl0, ub[0], s); s = fmaf(wl1, ub[1], s); s = fmaf(wl2, ub[2], s);
        s = fmaf(wl3, yb[0], s); s = fmaf(wl4, yb[1], s); s = fmaf(wl5, yb[2], s);
        sLift[lbb * LPITCH + lgl] = s * sigm(s);
    }
    __syncthreads();

    const size_t theta_base = (size_t)B * K * 3;

    // gh accumulators: start at 0 (h(-1) = 0 -> gh(0) = 0)
    u64 aR0 = 0, aR1 = 0, aR2 = 0, aR3 = 0;
    u64 aZ0 = 0, aZ1 = 0, aZ2 = 0, aZ3 = 0;
    u64 aN0 = 0, aN1 = 0, aN2 = 0, aN3 = 0;   // ghn
    float nu0 = 0, nu1 = 0, nu2 = 0, ndt = 0, nt0 = 0, nt1 = 0, nt2 = 0;
    bool nflag = false;

    for (int k = 0; k < K; k++) {
        if (t < MATT) {
            // ---- gx(k) (r,z merge into aR/aZ; n part separate) ----
            u64 aX0 = 0, aX1 = 0, aX2 = 0, aX3 = 0;
            {
                const ulonglong2* l0 = (const ulonglong2*)(sLift + 0 * LPITCH + LGAP * c);
                const ulonglong2* l1 = (const ulonglong2*)(sLift + 1 * LPITCH + LGAP * c);
                const ulonglong2* l2 = (const ulonglong2*)(sLift + 2 * LPITCH + LGAP * c);
                const ulonglong2* l3 = (const ulonglong2*)(sLift + 3 * LPITCH + LGAP * c);
#pragma unroll
                for (int j = 0; j < 4; j++) {
                    u64 wa = wr_[2 * j], wb = wr_[2 * j + 1];
                    u64 za = wz_[2 * j], zb = wz_[2 * j + 1];
                    u64 na = wn_[2 * j], nb = wn_[2 * j + 1];
                    ulonglong2 v0 = l0[j];
                    aR0 = fma2(wa, v0.x, aR0); aR0 = fma2(wb, v0.y, aR0);
                    aZ0 = fma2(za, v0.x, aZ0); aZ0 = fma2(zb, v0.y, aZ0);
                    aX0 = fma2(na, v0.x, aX0); aX0 = fma2(nb, v0.y, aX0);
                    ulonglong2 v1 = l1[j];
                    aR1 = fma2(wa, v1.x, aR1); aR1 = fma2(wb, v1.y, aR1);
                    aZ1 = fma2(za, v1.x, aZ1); aZ1 = fma2(zb, v1.y, aZ1);
                    aX1 = fma2(na, v1.x, aX1); aX1 = fma2(nb, v1.y, aX1);
                    ulonglong2 v2 = l2[j];
                    aR2 = fma2(wa, v2.x, aR2); aR2 = fma2(wb, v2.y, aR2);
                    aZ2 = fma2(za, v2.x, aZ2); aZ2 = fma2(zb, v2.y, aZ2);
                    aX2 = fma2(na, v2.x, aX2); aX2 = fma2(nb, v2.y, aX2);
                    ulonglong2 v3 = l3[j];
                    aR3 = fma2(wa, v3.x, aR3); aR3 = fma2(wb, v3.y, aR3);
                    aZ3 = fma2(za, v3.x, aZ3); aZ3 = fma2(zb, v3.y, aZ3);
                    aX3 = fma2(na, v3.x, aX3); aX3 = fma2(nb, v3.y, aX3);
                }
            }
            // ---- reduce across K-half pair (bfly ^1) ----
            float r0s = f2sum(aR0), r1s = f2sum(aR1), r2s = f2sum(aR2), r3s = f2sum(aR3);
            float z0s = f2sum(aZ0), z1s = f2sum(aZ1), z2s = f2sum(aZ2), z3s = f2sum(aZ3);
            float x0s = f2sum(aX0), x1s = f2sum(aX1), x2s = f2sum(aX2), x3s = f2sum(aX3);
            float n0s = f2sum(aN0), n1s = f2sum(aN1), n2s = f2sum(aN2), n3s = f2sum(aN3);
            r0s += __shfl_xor_sync(0xffffffffu, r0s, 1);
            r1s += __shfl_xor_sync(0xffffffffu, r1s, 1);
            r2s += __shfl_xor_sync(0xffffffffu, r2s, 1);
            r3s += __shfl_xor_sync(0xffffffffu, r3s, 1);
            z0s += __shfl_xor_sync(0xffffffffu, z0s, 1);
            z1s += __shfl_xor_sync(0xffffffffu, z1s, 1);
            z2s += __shfl_xor_sync(0xffffffffu, z2s, 1);
            z3s += __shfl_xor_sync(0xffffffffu, z3s, 1);
            x0s += __shfl_xor_sync(0xffffffffu, x0s, 1);
            x1s += __shfl_xor_sync(0xffffffffu, x1s, 1);
            x2s += __shfl_xor_sync(0xffffffffu, x2s, 1);
            x3s += __shfl_xor_sync(0xffffffffu, x3s, 1);
            n0s += __shfl_xor_sync(0xffffffffu, n0s, 1);
            n1s += __shfl_xor_sync(0xffffffffu, n1s, 1);
            n2s += __shfl_xor_sync(0xffffffffu, n2s, 1);
            n3s += __shfl_xor_sync(0xffffffffu, n3s, 1);
            // lane c handles batches 2c, 2c+1; compute gates + h_new locally
            float rA = c ? r2s : r0s, rB = c ? r3s : r1s;
            float zA = c ? z2s : z0s, zB = c ? z3s : z1s;
            float xA = c ? x2s : x0s, xB = c ? x3s : x1s;
            float nA = c ? n2s : n0s, nB = c ? n3s : n1s;
            const int bA = 2 * c, bB = 2 * c + 1;
            const int gi = i + ((i >> 6) << 2);
            {
                float r = sigm(rA + cr);
                float z = sigm(zA + cz);
                float n = tanh_f(xA + bxn + r * (nA + bhn));
                float ho = sH[bA * PITCH + gi];
                sH[bA * PITCH + gi] = (1.0f - z) * n + z * ho;
            }
            {
                float r = sigm(rB + cr);
                float z = sigm(zB + cz);
                float n = tanh_f(xB + bxn + r * (nB + bhn));
                float ho = sH[bB * PITCH + gi];
                sH[bB * PITCH + gi] = (1.0f - z) * n + z * ho;
            }
            aR0 = aR1 = aR2 = aR3 = 0;
            aZ0 = aZ1 = aZ2 = aZ3 = 0;
            aN0 = aN1 = aN2 = aN3 = 0;
        } else {
            // ---- prefetch step-(k+1) inputs ----
            nflag = false;
            if (g < 4 && (k + 1) < K) {
                int bg = bg0 + g;
                const float* up = u_seq + ((size_t)bg * K + (k + 1)) * 3;
                nu0 = up[0]; nu1 = up[1]; nu2 = up[2];
                ndt = dt_seq[(size_t)bg * K + (k + 1)];
                nflag = ((k + 1) % 50) == 0;
                if (nflag) {
                    const float* yp = y_seq + ((size_t)bg * K + k) * 3;
                    nt0 = yp[0]; nt1 = yp[1]; nt2 = yp[2];
                }
            }
        }
        __syncthreads();   // BAR_A: sH = h(k) visible

        if (t < MATT) {
            // ---- gh(k+1): W_hh x h(k), overlapped with aux tail ----
            const ulonglong2* wRp = (const ulonglong2*)(sWhh + i * PITCH + CGAP * c);
            const ulonglong2* wZp = (const ulonglong2*)(sWhh + (128 + i) * PITCH + CGAP * c);
            const ulonglong2* wNp = (const ulonglong2*)(sWhh + (256 + i) * PITCH + CGAP * c);
            const ulonglong2* x0 = (const ulonglong2*)(sH + 0 * PITCH + CGAP * c);
            const ulonglong2* x1 = (const ulonglong2*)(sH + 1 * PITCH + CGAP * c);
            const ulonglong2* x2 = (const ulonglong2*)(sH + 2 * PITCH + CGAP * c);
            const ulonglong2* x3 = (const ulonglong2*)(sH + 3 * PITCH + CGAP * c);
#pragma unroll
            for (int j = 0; j < 16; j++) {
                ulonglong2 wR = wRp[j], wZ = wZp[j], wN = wNp[j];
                ulonglong2 v0 = x0[j];
                aR0 = fma2(wR.x, v0.x, aR0); aR0 = fma2(wR.y, v0.y, aR0);
                aZ0 = fma2(wZ.x, v0.x, aZ0); aZ0 = fma2(wZ.y, v0.y, aZ0);
                aN0 = fma2(wN.x, v0.x, aN0); aN0 = fma2(wN.y, v0.y, aN0);
                ulonglong2 v1 = x1[j];
                aR1 = fma2(wR.x, v1.x, aR1); aR1 = fma2(wR.y, v1.y, aR1);
                aZ1 = fma2(wZ.x, v1.x, aZ1); aZ1 = fma2(wZ.y, v1.y, aZ1);
                aN1 = fma2(wN.x, v1.x, aN1); aN1 = fma2(wN.y, v1.y, aN1);
                ulonglong2 v2 = x2[j];
                aR2 = fma2(wR.x, v2.x, aR2); aR2 = fma2(wR.y, v2.y, aR2);
                aZ2 = fma2(wZ.x, v2.x, aZ2); aZ2 = fma2(wZ.y, v2.y, aZ2);
                aN2 = fma2(wN.x, v2.x, aN2); aN2 = fma2(wN.y, v2.y, aN2);
                ulonglong2 v3 = x3[j];
                aR3 = fma2(wR.x, v3.x, aR3); aR3 = fma2(wR.y, v3.y, aR3);
                aZ3 = fma2(wZ.x, v3.x, aZ3); aZ3 = fma2(wZ.y, v3.y, aZ3);
                aN3 = fma2(wN.x, v3.x, aN3); aN3 = fma2(wN.y, v3.y, aN3);
            }
        } else {
            // ---- tail(k): head + RK4, then lift(k+1) ----
            float thv = 0.f;
            if (g < 20) {
                u64 s0 = 0, s1 = 0;
#pragma unroll
                for (int half = 0; half < 2; half++) {
                    const ulonglong2* hr = (const ulonglong2*)(sH + hbh * PITCH + CGAP * half);
                    const ulonglong2* wp = (const ulonglong2*)(sWhd + hph * PITCH + 64 * half);
#pragma unroll
                    for (int jb = 0; jb < 16; jb++) {
                        ulonglong2 h4 = hr[jb];
                        ulonglong2 w4 = wp[jb];
                        s0 = fma2(w4.x, h4.x, s0);
                        s1 = fma2(w4.y, h4.y, s1);
                    }
                }
                float s = f2sum(s0) + f2sum(s1) + bhd;
                thv = 0.001f + 1.999f * sigm(s);
                out[theta_base + ((size_t)(bg0 + hbh) * K + k) * 5 + hph] = thv;
            }
            if (g < 32) {   // warp 8 only (uniform)
                float th0 = __shfl_sync(0xffffffffu, thv, g * 5 + 0);
                float th1 = __shfl_sync(0xffffffffu, thv, g * 5 + 1);
                float th2 = __shfl_sync(0xffffffffu, thv, g * 5 + 2);
                float th3 = __shfl_sync(0xffffffffu, thv, g * 5 + 3);
                float th4 = __shfl_sync(0xffffffffu, thv, g * 5 + 4);
                if (g < 4) {
                    yf0 += cu0 * J00 + cu1 * J10 + cu2 * J20;
                    yf2 += cu0 * J01 + cu1 * J11 + cu2 * J21;
                    yf4 += cu0 * J02 + cu1 * J12 + cu2 * J22;
                    float h  = cdt;
                    float hhf = 0.5f * h;
#define RHS(A_, Bv, C_, D_, E_, d0, d1, d2, d3, d4)                      \
                    {                                                    \
                        float r1 = th0 * (A_) * (Bv);                    \
                        float r2 = th1 * (C_);                           \
                        float r3 = th2 * (C_) * (D_);                    \
                        float r4 = th3 * (E_);                           \
                        float r5 = th4 * (A_);                           \
                        d0 = -r1 - r5; d1 = -r1 + r2; d2 = r1 - r2 - r3; \
                        d3 = -r3 + r4; d4 = r3 - r4 + r5;                \
                    }
                    float a0, a1, a2, a3, a4;
                    RHS(yf0, yf1, yf2, yf3, yf4, a0, a1, a2, a3, a4);
                    float t0 = yf0 + hhf * a0, t1 = yf1 + hhf * a1, t2 = yf2 + hhf * a2,
                          t3 = yf3 + hhf * a3, t4 = yf4 + hhf * a4;
                    float b0, b1, b2, b3, b4v;
                    RHS(t0, t1, t2, t3, t4, b0, b1, b2, b3, b4v);
                    t0 = yf0 + hhf * b0; t1 = yf1 + hhf * b1; t2 = yf2 + hhf * b2;
                    t3 = yf3 + hhf * b3; t4 = yf4 + hhf * b4v;
                    float c0, c1, c2, c3, c4;
                    RHS(t0, t1, t2, t3, t4, c0, c1, c2, c3, c4);
                    t0 = yf0 + h * c0; t1 = yf1 + h * c1; t2 = yf2 + h * c2;
                    t3 = yf3 + h * c3; t4 = yf4 + h * c4;
                    float d0, d1, d2, d3, d4;
                    RHS(t0, t1, t2, t3, t4, d0, d1, d2, d3, d4);
#undef RHS
                    float s6 = h * (1.0f / 6.0f);
                    yf0 = fmaxf(yf0 + s6 * (a0 + 2.f * b0 + 2.f * c0 + d0), 0.f);
                    yf1 = fmaxf(yf1 + s6 * (a1 + 2.f * b1 + 2.f * c1 + d1), 0.f);
                    yf2 = fmaxf(yf2 + s6 * (a2 + 2.f * b2 + 2.f * c2 + d2), 0.f);
                    yf3 = fmaxf(yf3 + s6 * (a3 + 2.f * b3 + 2.f * c3 + d3), 0.f);
                    yf4 = fmaxf(yf4 + s6 * (a4 + 2.f * b4v + 2.f * c4 + d4), 0.f);

                    int bg = bg0 + g;
                    float* yo = out + ((size_t)bg * K + k) * 3;
                    yo[0] = yf0; yo[1] = yf2; yo[2] = yf4;
                    sYobs[g * 4 + 0] = yf0; sYobs[g * 4 + 1] = yf2; sYobs[g * 4 + 2] = yf4;
                    if (k + 1 < K) {
                        sU[g * 4 + 0] = nu0; sU[g * 4 + 1] = nu1; sU[g * 4 + 2] = nu2;
                        if (nflag) {
                            sYtf[g * 4 + 0] = nt0; sYtf[g * 4 + 1] = nt1; sYtf[g * 4 + 2] = nt2;
                        }
                        cu0 = nu0; cu1 = nu1; cu2 = nu2; cdt = ndt;
                    }
                }
            }
            asm volatile("bar.sync 1, 128;" ::: "memory");   // aux-only barrier
            // ---- lift(k+1) ----
            {
                int kk1 = k + 1;
                bool lf = (kk1 % 50) == 0;
                const float* ub = sU + lbb * 4;
                const float* yb = lf ? (sYtf + lbb * 4) : (sYobs + lbb * 4);
                float s = blf;
                s = fmaf(wl0, ub[0], s); s = fmaf(wl1, ub[1], s); s = fmaf(wl2, ub[2], s);
                s = fmaf(wl3, yb[0], s); s = fmaf(wl4, yb[1], s); s = fmaf(wl5, yb[2], s);
                sLift[lbb * LPITCH + lgl] = s * sigm(s);
            }
        }
        __syncthreads();   // BAR_B: sLift(k+1) visible, gh(k+1) done
    }
}

extern "C" void kernel_launch(void* const* d_in, const int* in_sizes, int n_in,
                              void* d_out, int out_size)
{
    const float* y0     = (const float*)d_in[0];
    const float* u_seq  = (const float*)d_in[1];
    const float* dt_seq = (const float*)d_in[2];
    const float* y_seq  = (const float*)d_in[3];
    const float* W_lift = (const float*)d_in[4];
    const float* b_lift = (const float*)d_in[5];
    const float* W_ih   = (const float*)d_in[6];
    const float* W_hh   = (const float*)d_in[7];
    const float* b_ih   = (const float*)d_in[8];
    const float* b_hh   = (const float*)d_in[9];
    const float* W_head = (const float*)d_in[10];
    const float* b_head = (const float*)d_in[11];
    const float* u2y    = (const float*)d_in[12];
    float* out = (float*)d_out;

    int B = in_sizes[0] / 3;
    int K = in_sizes[2] / B;

    cudaFuncSetAttribute(krnn_kernel, cudaFuncAttributeMaxDynamicSharedMemorySize, SMEM_BYTES);
    krnn_kernel<<<B / 4, THREADS, SMEM_BYTES>>>(
        y0, u_seq, dt_seq, y_seq, W_lift, b_lift, W_ih, W_hh,
        b_ih, b_hh, W_head, b_head, u2y, out, B, K);
}

// round 6
// speedup vs baseline: 1.7150x; 1.0004x over previous
#include <cuda_runtime.h>
#include <math.h>

// KineticsRNN R5: warp-specialized persistent recurrence, fp32 f32x2.
// 128 CTAs x 4 batch. 256 "mat" threads: thread (i=t>>1, c=t&1) owns gate rows
// (r_i, z_i, n_i) for K-half c -> shfl.bfly(1) gives full gates, h_new computed
// locally (no cross-thread gate handoff). 128 "aux" threads run head+RK4+lift
// overlapped with the mat warps' gh of the next step. 2 full barriers/step.

#define THREADS 384
#define MATT 256
#define HDIM 128
#define PITCH 136     // W_hh / sH / sWhd row pitch (words); K-chunk1 at +68
#define CGAP 68
#define LPITCH 40     // sLift row pitch; chunk1 at +20
#define LGAP 20

#define SMEM_FLOATS (384*PITCH + 4*PITCH + 4*LPITCH + 5*PITCH + 16 + 16 + 16)
#define SMEM_BYTES  (SMEM_FLOATS * 4)

typedef unsigned long long u64;

__device__ __forceinline__ u64 fma2(u64 a, u64 b, u64 c) {
    u64 d;
    asm("fma.rn.f32x2 %0, %1, %2, %3;" : "=l"(d) : "l"(a), "l"(b), "l"(c));
    return d;
}
__device__ __forceinline__ float f2sum(u64 v) {
    float2 f;
    asm("mov.b64 {%0, %1}, %2;" : "=f"(f.x), "=f"(f.y) : "l"(v));
    return f.x + f.y;
}
__device__ __forceinline__ float sigm(float x) {
    return __fdividef(1.0f, 1.0f + __expf(-x));
}
__device__ __forceinline__ float tanh_f(float x) {
    return 1.0f - __fdividef(2.0f, __expf(2.0f * x) + 1.0f);
}

__global__ __launch_bounds__(THREADS, 1)
void krnn_kernel(const float* __restrict__ y0,
                 const float* __restrict__ u_seq,
                 const float* __restrict__ dt_seq,
                 const float* __restrict__ y_seq,
                 const float* __restrict__ W_lift,
                 const float* __restrict__ b_lift,
                 const float* __restrict__ W_ih,
                 const float* __restrict__ W_hh,
                 const float* __restrict__ b_ih,
                 const float* __restrict__ b_hh,
                 const float* __restrict__ W_head,
                 const float* __restrict__ b_head,
                 const float* __restrict__ u2y,
                 float* __restrict__ out,
                 int B, int K)
{
    extern __shared__ float sm[];
    float* sWhh  = sm;                       // 384*136 (gapped rows)
    float* sH    = sWhh + 384 * PITCH;       // 4*136 (gapped)
    float* sLift = sH + 4 * PITCH;           // 4*40 (gapped)
    float* sWhd  = sLift + 4 * LPITCH;       // 5*136
    float* sU    = sWhd + 5 * PITCH;         // 4*4
    float* sYobs = sU + 16;                  // 4*4
    float* sYtf  = sYobs + 16;               // 4*4

    const int t   = threadIdx.x;
    const int bg0 = blockIdx.x * 4;

    // ---- stage W_hh gapped: word(row,k) = row*136 + k + 4*(k>=64) ----
    {
        const float4* src = (const float4*)W_hh;
        for (int idx = t; idx < 384 * 32; idx += THREADS) {
            int row = idx >> 5, kb = idx & 31;
            int dst = row * PITCH + 4 * kb + ((kb >> 4) << 2);
            *(float4*)(sWhh + dst) = src[idx];
        }
    }
    for (int idx = t; idx < 5 * HDIM; idx += THREADS)
        sWhd[(idx / HDIM) * PITCH + (idx % HDIM)] = W_head[idx];

    // ================= mat-thread persistent state =================
    const int i = t >> 1, c = t & 1;
    u64 wr_[8], wz_[8], wn_[8];
    float cr = 0, cz = 0, bxn = 0, bhn = 0;
    if (t < MATT) {
        const ulonglong2* pr = (const ulonglong2*)(W_ih + (size_t)i * 32 + 16 * c);
        const ulonglong2* pz = (const ulonglong2*)(W_ih + (size_t)(128 + i) * 32 + 16 * c);
        const ulonglong2* pn = (const ulonglong2*)(W_ih + (size_t)(256 + i) * 32 + 16 * c);
#pragma unroll
        for (int j = 0; j < 4; j++) {
            ulonglong2 vr = pr[j]; wr_[2 * j] = vr.x; wr_[2 * j + 1] = vr.y;
            ulonglong2 vz = pz[j]; wz_[2 * j] = vz.x; wz_[2 * j + 1] = vz.y;
            ulonglong2 vn = pn[j]; wn_[2 * j] = vn.x; wn_[2 * j + 1] = vn.y;
        }
        cr  = b_ih[i] + b_hh[i];
        cz  = b_ih[128 + i] + b_hh[128 + i];
        bxn = b_ih[256 + i];
        bhn = b_hh[256 + i];
    }

    // ================= aux-thread persistent state =================
    const int g   = t - 256;                  // aux index (valid t>=256)
    const int hbh = g / 5, hph = g % 5;       // head mapping (g<20)
    const int lr  = g >> 2, lbb = g & 3;      // lift mapping
    const int lgl = lr + ((lr >> 4) << 2);
    float bhd = 0.f;
    float wl0 = 0, wl1 = 0, wl2 = 0, wl3 = 0, wl4 = 0, wl5 = 0, blf = 0;
    float yf0 = 0, yf1 = 0, yf2 = 0, yf3 = 0, yf4 = 0;
    float J00 = 0, J01 = 0, J02 = 0, J10 = 0, J11 = 0, J12 = 0, J20 = 0, J21 = 0, J22 = 0;
    float cu0 = 0, cu1 = 0, cu2 = 0, cdt = 0;
    if (t >= MATT) {
        if (g < 20) bhd = b_head[hph];
        wl0 = W_lift[lr * 6 + 0]; wl1 = W_lift[lr * 6 + 1]; wl2 = W_lift[lr * 6 + 2];
        wl3 = W_lift[lr * 6 + 3]; wl4 = W_lift[lr * 6 + 4]; wl5 = W_lift[lr * 6 + 5];
        blf = b_lift[lr];
        if (g < 4) {
            int bg = bg0 + g;
            yf0 = y0[bg * 3 + 0]; yf2 = y0[bg * 3 + 1]; yf4 = y0[bg * 3 + 2];
            J00 = u2y[0]; J01 = u2y[1]; J02 = u2y[2];
            J10 = u2y[3]; J11 = u2y[4]; J12 = u2y[5];
            J20 = u2y[6]; J21 = u2y[7]; J22 = u2y[8];
            const float* up = u_seq + (size_t)bg * K * 3;
            cu0 = up[0]; cu1 = up[1]; cu2 = up[2];
            cdt = dt_seq[(size_t)bg * K];
            sU[g * 4 + 0] = cu0; sU[g * 4 + 1] = cu1; sU[g * 4 + 2] = cu2;
            sYobs[g * 4 + 0] = yf0; sYobs[g * 4 + 1] = yf2; sYobs[g * 4 + 2] = yf4;
        }
    }
    for (int idx = t; idx < 4 * PITCH; idx += THREADS) sH[idx] = 0.f;
    __syncthreads();

    // ---- prologue: lift(0) ----
    if (t >= MATT) {
        const float* ub = sU + lbb * 4;
        const float* yb = sYobs + lbb * 4;
        float s = blf;
        s = fmaf(wl0, ub[0], s); s = fmaf(wl1, ub[1], s); s = fmaf(wl2, ub[2], s);
        s = fmaf(wl3, yb[0], s); s = fmaf(wl4, yb[1], s); s = fmaf(wl5, yb[2], s);
        sLift[lbb * LPITCH + lgl] = s * sigm(s);
    }
    __syncthreads();

    const size_t theta_base = (size_t)B * K * 3;

    // gh accumulators: start at 0 (h(-1) = 0 -> gh(0) = 0)
    u64 aR0 = 0, aR1 = 0, aR2 = 0, aR3 = 0;
    u64 aZ0 = 0, aZ1 = 0, aZ2 = 0, aZ3 = 0;
    u64 aN0 = 0, aN1 = 0, aN2 = 0, aN3 = 0;   // ghn
    float nu0 = 0, nu1 = 0, nu2 = 0, ndt = 0, nt0 = 0, nt1 = 0, nt2 = 0;
    bool nflag = false;

    for (int k = 0; k < K; k++) {
        if (t < MATT) {
            // ---- gx(k) (r,z merge into aR/aZ; n part separate) ----
            u64 aX0 = 0, aX1 = 0, aX2 = 0, aX3 = 0;
            {
                const ulonglong2* l0 = (const ulonglong2*)(sLift + 0 * LPITCH + LGAP * c);
                const ulonglong2* l1 = (const ulonglong2*)(sLift + 1 * LPITCH + LGAP * c);
                const ulonglong2* l2 = (const ulonglong2*)(sLift + 2 * LPITCH + LGAP * c);
                const ulonglong2* l3 = (const ulonglong2*)(sLift + 3 * LPITCH + LGAP * c);
#pragma unroll
                for (int j = 0; j < 4; j++) {
                    u64 wa = wr_[2 * j], wb = wr_[2 * j + 1];
                    u64 za = wz_[2 * j], zb = wz_[2 * j + 1];
                    u64 na = wn_[2 * j], nb = wn_[2 * j + 1];
                    ulonglong2 v0 = l0[j];
                    aR0 = fma2(wa, v0.x, aR0); aR0 = fma2(wb, v0.y, aR0);
                    aZ0 = fma2(za, v0.x, aZ0); aZ0 = fma2(zb, v0.y, aZ0);
                    aX0 = fma2(na, v0.x, aX0); aX0 = fma2(nb, v0.y, aX0);
                    ulonglong2 v1 = l1[j];
                    aR1 = fma2(wa, v1.x, aR1); aR1 = fma2(wb, v1.y, aR1);
                    aZ1 = fma2(za, v1.x, aZ1); aZ1 = fma2(zb, v1.y, aZ1);
                    aX1 = fma2(na, v1.x, aX1); aX1 = fma2(nb, v1.y, aX1);
                    ulonglong2 v2 = l2[j];
                    aR2 = fma2(wa, v2.x, aR2); aR2 = fma2(wb, v2.y, aR2);
                    aZ2 = fma2(za, v2.x, aZ2); aZ2 = fma2(zb, v2.y, aZ2);
                    aX2 = fma2(na, v2.x, aX2); aX2 = fma2(nb, v2.y, aX2);
                    ulonglong2 v3 = l3[j];
                    aR3 = fma2(wa, v3.x, aR3); aR3 = fma2(wb, v3.y, aR3);
                    aZ3 = fma2(za, v3.x, aZ3); aZ3 = fma2(zb, v3.y, aZ3);
                    aX3 = fma2(na, v3.x, aX3); aX3 = fma2(nb, v3.y, aX3);
                }
            }
            // ---- reduce across K-half pair (bfly ^1) ----
            float r0s = f2sum(aR0), r1s = f2sum(aR1), r2s = f2sum(aR2), r3s = f2sum(aR3);
            float z0s = f2sum(aZ0), z1s = f2sum(aZ1), z2s = f2sum(aZ2), z3s = f2sum(aZ3);
            float x0s = f2sum(aX0), x1s = f2sum(aX1), x2s = f2sum(aX2), x3s = f2sum(aX3);
            float n0s = f2sum(aN0), n1s = f2sum(aN1), n2s = f2sum(aN2), n3s = f2sum(aN3);
            r0s += __shfl_xor_sync(0xffffffffu, r0s, 1);
            r1s += __shfl_xor_sync(0xffffffffu, r1s, 1);
            r2s += __shfl_xor_sync(0xffffffffu, r2s, 1);
            r3s += __shfl_xor_sync(0xffffffffu, r3s, 1);
            z0s += __shfl_xor_sync(0xffffffffu, z0s, 1);
            z1s += __shfl_xor_sync(0xffffffffu, z1s, 1);
            z2s += __shfl_xor_sync(0xffffffffu, z2s, 1);
            z3s += __shfl_xor_sync(0xffffffffu, z3s, 1);
            x0s += __shfl_xor_sync(0xffffffffu, x0s, 1);
            x1s += __shfl_xor_sync(0xffffffffu, x1s, 1);
            x2s += __shfl_xor_sync(0xffffffffu, x2s, 1);
            x3s += __shfl_xor_sync(0xffffffffu, x3s, 1);
            n0s += __shfl_xor_sync(0xffffffffu, n0s, 1);
            n1s += __shfl_xor_sync(0xffffffffu, n1s, 1);
            n2s += __shfl_xor_sync(0xffffffffu, n2s, 1);
            n3s += __shfl_xor_sync(0xffffffffu, n3s, 1);
            // lane c handles batches 2c, 2c+1; compute gates + h_new locally
            float rA = c ? r2s : r0s, rB = c ? r3s : r1s;
            float zA = c ? z2s : z0s, zB = c ? z3s : z1s;
            float xA = c ? x2s : x0s, xB = c ? x3s : x1s;
            float nA = c ? n2s : n0s, nB = c ? n3s : n1s;
            const int bA = 2 * c, bB = 2 * c + 1;
            const int gi = i + ((i >> 6) << 2);
            {
                float r = sigm(rA + cr);
                float z = sigm(zA + cz);
                float n = tanh_f(xA + bxn + r * (nA + bhn));
                float ho = sH[bA * PITCH + gi];
                sH[bA * PITCH + gi] = (1.0f - z) * n + z * ho;
            }
            {
                float r = sigm(rB + cr);
                float z = sigm(zB + cz);
                float n = tanh_f(xB + bxn + r * (nB + bhn));
                float ho = sH[bB * PITCH + gi];
                sH[bB * PITCH + gi] = (1.0f - z) * n + z * ho;
            }
            aR0 = aR1 = aR2 = aR3 = 0;
            aZ0 = aZ1 = aZ2 = aZ3 = 0;
            aN0 = aN1 = aN2 = aN3 = 0;
        } else {
            // ---- prefetch step-(k+1) inputs ----
            nflag = false;
            if (g < 4 && (k + 1) < K) {
                int bg = bg0 + g;
                const float* up = u_seq + ((size_t)bg * K + (k + 1)) * 3;
                nu0 = up[0]; nu1 = up[1]; nu2 = up[2];
                ndt = dt_seq[(size_t)bg * K + (k + 1)];
                nflag = ((k + 1) % 50) == 0;
                if (nflag) {
                    const float* yp = y_seq + ((size_t)bg * K + k) * 3;
                    nt0 = yp[0]; nt1 = yp[1]; nt2 = yp[2];
                }
            }
        }
        __syncthreads();   // BAR_A: sH = h(k) visible

        if (t < MATT) {
            // ---- gh(k+1): W_hh x h(k), overlapped with aux tail ----
            const ulonglong2* wRp = (const ulonglong2*)(sWhh + i * PITCH + CGAP * c);
            const ulonglong2* wZp = (const ulonglong2*)(sWhh + (128 + i) * PITCH + CGAP * c);
            const ulonglong2* wNp = (const ulonglong2*)(sWhh + (256 + i) * PITCH + CGAP * c);
            const ulonglong2* x0 = (const ulonglong2*)(sH + 0 * PITCH + CGAP * c);
            const ulonglong2* x1 = (const ulonglong2*)(sH + 1 * PITCH + CGAP * c);
            const ulonglong2* x2 = (const ulonglong2*)(sH + 2 * PITCH + CGAP * c);
            const ulonglong2* x3 = (const ulonglong2*)(sH + 3 * PITCH + CGAP * c);
#pragma unroll
            for (int j = 0; j < 16; j++) {
                ulonglong2 wR = wRp[j], wZ = wZp[j], wN = wNp[j];
                ulonglong2 v0 = x0[j];
                aR0 = fma2(wR.x, v0.x, aR0); aR0 = fma2(wR.y, v0.y, aR0);
                aZ0 = fma2(wZ.x, v0.x, aZ0); aZ0 = fma2(wZ.y, v0.y, aZ0);
                aN0 = fma2(wN.x, v0.x, aN0); aN0 = fma2(wN.y, v0.y, aN0);
                ulonglong2 v1 = x1[j];
                aR1 = fma2(wR.x, v1.x, aR1); aR1 = fma2(wR.y, v1.y, aR1);
                aZ1 = fma2(wZ.x, v1.x, aZ1); aZ1 = fma2(wZ.y, v1.y, aZ1);
                aN1 = fma2(wN.x, v1.x, aN1); aN1 = fma2(wN.y, v1.y, aN1);
                ulonglong2 v2 = x2[j];
                aR2 = fma2(wR.x, v2.x, aR2); aR2 = fma2(wR.y, v2.y, aR2);
                aZ2 = fma2(wZ.x, v2.x, aZ2); aZ2 = fma2(wZ.y, v2.y, aZ2);
                aN2 = fma2(wN.x, v2.x, aN2); aN2 = fma2(wN.y, v2.y, aN2);
                ulonglong2 v3 = x3[j];
                aR3 = fma2(wR.x, v3.x, aR3); aR3 = fma2(wR.y, v3.y, aR3);
                aZ3 = fma2(wZ.x, v3.x, aZ3); aZ3 = fma2(wZ.y, v3.y, aZ3);
                aN3 = fma2(wN.x, v3.x, aN3); aN3 = fma2(wN.y, v3.y, aN3);
            }
        } else {
            // ---- tail(k): head + RK4, then lift(k+1) ----
            float thv = 0.f;
            if (g < 20) {
                u64 s0 = 0, s1 = 0;
#pragma unroll
                for (int half = 0; half < 2; half++) {
                    const ulonglong2* hr = (const ulonglong2*)(sH + hbh * PITCH + CGAP * half);
                    const ulonglong2* wp = (const ulonglong2*)(sWhd + hph * PITCH + 64 * half);
#pragma unroll
                    for (int jb = 0; jb < 16; jb++) {
                        ulonglong2 h4 = hr[jb];
                        ulonglong2 w4 = wp[jb];
                        s0 = fma2(w4.x, h4.x, s0);
                        s1 = fma2(w4.y, h4.y, s1);
                    }
                }
                float s = f2sum(s0) + f2sum(s1) + bhd;
                thv = 0.001f + 1.999f * sigm(s);
                out[theta_base + ((size_t)(bg0 + hbh) * K + k) * 5 + hph] = thv;
            }
            if (g < 32) {   // warp 8 only (uniform)
                float th0 = __shfl_sync(0xffffffffu, thv, g * 5 + 0);
                float th1 = __shfl_sync(0xffffffffu, thv, g * 5 + 1);
                float th2 = __shfl_sync(0xffffffffu, thv, g * 5 + 2);
                float th3 = __shfl_sync(0xffffffffu, thv, g * 5 + 3);
                float th4 = __shfl_sync(0xffffffffu, thv, g * 5 + 4);
                if (g < 4) {
                    yf0 += cu0 * J00 + cu1 * J10 + cu2 * J20;
                    yf2 += cu0 * J01 + cu1 * J11 + cu2 * J21;
                    yf4 += cu0 * J02 + cu1 * J12 + cu2 * J22;
                    float h  = cdt;
                    float hhf = 0.5f * h;
#define RHS(A_, Bv, C_, D_, E_, d0, d1, d2, d3, d4)                      \
                    {                                                    \
                        float r1 = th0 * (A_) * (Bv);                    \
                        float r2 = th1 * (C_);                           \
                        float r3 = th2 * (C_) * (D_);                    \
                        float r4 = th3 * (E_);                           \
                        float r5 = th4 * (A_);                           \
                        d0 = -r1 - r5; d1 = -r1 + r2; d2 = r1 - r2 - r3; \
                        d3 = -r3 + r4; d4 = r3 - r4 + r5;                \
                    }
                    float a0, a1, a2, a3, a4;
                    RHS(yf0, yf1, yf2, yf3, yf4, a0, a1, a2, a3, a4);
                    float t0 = yf0 + hhf * a0, t1 = yf1 + hhf * a1, t2 = yf2 + hhf * a2,
                          t3 = yf3 + hhf * a3, t4 = yf4 + hhf * a4;
                    float b0, b1, b2, b3, b4v;
                    RHS(t0, t1, t2, t3, t4, b0, b1, b2, b3, b4v);
                    t0 = yf0 + hhf * b0; t1 = yf1 + hhf * b1; t2 = yf2 + hhf * b2;
                    t3 = yf3 + hhf * b3; t4 = yf4 + hhf * b4v;
                    float c0, c1, c2, c3, c4;
                    RHS(t0, t1, t2, t3, t4, c0, c1, c2, c3, c4);
                    t0 = yf0 + h * c0; t1 = yf1 + h * c1; t2 = yf2 + h * c2;
                    t3 = yf3 + h * c3; t4 = yf4 + h * c4;
                    float d0, d1, d2, d3, d4;
                    RHS(t0, t1, t2, t3, t4, d0, d1, d2, d3, d4);
#undef RHS
                    float s6 = h * (1.0f / 6.0f);
                    yf0 = fmaxf(yf0 + s6 * (a0 + 2.f * b0 + 2.f * c0 + d0), 0.f);
                    yf1 = fmaxf(yf1 + s6 * (a1 + 2.f * b1 + 2.f * c1 + d1), 0.f);
                    yf2 = fmaxf(yf2 + s6 * (a2 + 2.f * b2 + 2.f * c2 + d2), 0.f);
                    yf3 = fmaxf(yf3 + s6 * (a3 + 2.f * b3 + 2.f * c3 + d3), 0.f);
                    yf4 = fmaxf(yf4 + s6 * (a4 + 2.f * b4v + 2.f * c4 + d4), 0.f);

                    int bg = bg0 + g;
                    float* yo = out + ((size_t)bg * K + k) * 3;
                    yo[0] = yf0; yo[1] = yf2; yo[2] = yf4;
                    sYobs[g * 4 + 0] = yf0; sYobs[g * 4 + 1] = yf2; sYobs[g * 4 + 2] = yf4;
                    if (k + 1 < K) {
                        sU[g * 4 + 0] = nu0; sU[g * 4 + 1] = nu1; sU[g * 4 + 2] = nu2;
                        if (nflag) {
                            sYtf[g * 4 + 0] = nt0; sYtf[g * 4 + 1] = nt1; sYtf[g * 4 + 2] = nt2;
                        }
                        cu0 = nu0; cu1 = nu1; cu2 = nu2; cdt = ndt;
                    }
                }
            }
            asm volatile("bar.sync 1, 128;" ::: "memory");   // aux-only barrier
            // ---- lift(k+1) ----
            {
                int kk1 = k + 1;
                bool lf = (kk1 % 50) == 0;
                const float* ub = sU + lbb * 4;
                const float* yb = lf ? (sYtf + lbb * 4) : (sYobs + lbb * 4);
                float s = blf;
                s = fmaf(wl0, ub[0], s); s = fmaf(wl1, ub[1], s); s = fmaf(wl2, ub[2], s);
                s = fmaf(wl3, yb[0], s); s = fmaf(wl4, yb[1], s); s = fmaf(wl5, yb[2], s);
                sLift[lbb * LPITCH + lgl] = s * sigm(s);
            }
        }
        __syncthreads();   // BAR_B: sLift(k+1) visible, gh(k+1) done
    }
}

extern "C" void kernel_launch(void* const* d_in, const int* in_sizes, int n_in,
                              void* d_out, int out_size)
{
    const float* y0     = (const float*)d_in[0];
    const float* u_seq  = (const float*)d_in[1];
    const float* dt_seq = (const float*)d_in[2];
    const float* y_seq  = (const float*)d_in[3];
    const float* W_lift = (const float*)d_in[4];
    const float* b_lift = (const float*)d_in[5];
    const float* W_ih   = (const float*)d_in[6];
    const float* W_hh   = (const float*)d_in[7];
    const float* b_ih   = (const float*)d_in[8];
    const float* b_hh   = (const float*)d_in[9];
    const float* W_head = (const float*)d_in[10];
    const float* b_head = (const float*)d_in[11];
    const float* u2y    = (const float*)d_in[12];
    float* out = (float*)d_out;

    int B = in_sizes[0] / 3;
    int K = in_sizes[2] / B;

    cudaFuncSetAttribute(krnn_kernel, cudaFuncAttributeMaxDynamicSharedMemorySize, SMEM_BYTES);
    krnn_kernel<<<B / 4, THREADS, SMEM_BYTES>>>(
        y0, u_seq, dt_seq, y_seq, W_lift, b_lift, W_ih, W_hh,
        b_ih, b_hh, W_head, b_head, u2y, out, B, K);
}